// round 1
// baseline (speedup 1.0000x reference)
#include <cuda_runtime.h>
#include <cuda_bf16.h>
#include <math.h>

// Problem constants
#define BATCH 2
#define SEQ   2048
#define DMODEL 1024
#define NHEAD 16
#define HDIM  64
#define ROWS  (BATCH*SEQ)          // 4096
#define QKV_N (3*DMODEL)           // 3072

// Scratch (no cudaMalloc allowed)
__device__ float g_qkv[(size_t)ROWS * QKV_N];   // 48 MB: [row][3*D], q|k|v per row
__device__ float g_ctx[(size_t)ROWS * DMODEL];  // 16 MB: [b*S+s][h*64+d]

// ---------------------------------------------------------------------------
// SGEMM: C[M,N] = A[M,K] @ B[K,N] (+bias[N]), all fp32 row-major.
// 128x128 block tile, BK=8, 256 threads, 8x8 per-thread microtile.
// M,N multiples of 128; K multiple of 8 (true for all our shapes).
// ---------------------------------------------------------------------------
__global__ __launch_bounds__(256) void sgemm128(
    const float* __restrict__ A, const float* __restrict__ B,
    const float* __restrict__ bias, float* __restrict__ C,
    int M, int N, int K)
{
    __shared__ float As[8][132];   // transposed A tile, padded
    __shared__ float Bs[8][132];

    const int tid = threadIdx.x;
    const int bx = blockIdx.x, by = blockIdx.y;
    const int tx = tid & 15, ty = tid >> 4;

    // gmem load mapping
    const int arow = tid >> 1;            // 0..127
    const int acol = (tid & 1) * 4;       // 0 or 4
    const int brow = tid >> 5;            // 0..7
    const int bcol = (tid & 31) * 4;      // 0..124

    const float* Aptr = A + (size_t)(by * 128 + arow) * K + acol;
    const float* Bptr = B + (size_t)brow * N + bx * 128 + bcol;

    float4 areg = *(const float4*)Aptr;
    float4 breg = *(const float4*)Bptr;

    float acc[8][8];
    #pragma unroll
    for (int i = 0; i < 8; i++)
        #pragma unroll
        for (int j = 0; j < 8; j++) acc[i][j] = 0.f;

    const int nk = K >> 3;
    for (int kt = 0; kt < nk; kt++) {
        __syncthreads();
        As[acol + 0][arow] = areg.x;
        As[acol + 1][arow] = areg.y;
        As[acol + 2][arow] = areg.z;
        As[acol + 3][arow] = areg.w;
        *(float4*)&Bs[brow][bcol] = breg;
        __syncthreads();

        if (kt + 1 < nk) {  // prefetch next tile while computing
            areg = *(const float4*)(Aptr + (size_t)(kt + 1) * 8);
            breg = *(const float4*)(Bptr + (size_t)(kt + 1) * 8 * N);
        }

        #pragma unroll
        for (int k = 0; k < 8; k++) {
            float4 a0 = *(const float4*)&As[k][ty * 8];
            float4 a1 = *(const float4*)&As[k][ty * 8 + 4];
            float4 b0 = *(const float4*)&Bs[k][tx * 8];
            float4 b1 = *(const float4*)&Bs[k][tx * 8 + 4];
            float av[8] = {a0.x, a0.y, a0.z, a0.w, a1.x, a1.y, a1.z, a1.w};
            float bv[8] = {b0.x, b0.y, b0.z, b0.w, b1.x, b1.y, b1.z, b1.w};
            #pragma unroll
            for (int i = 0; i < 8; i++)
                #pragma unroll
                for (int j = 0; j < 8; j++)
                    acc[i][j] += av[i] * bv[j];
        }
    }

    // epilogue
    const int crow0 = by * 128 + ty * 8;
    const int ccol0 = bx * 128 + tx * 8;
    float bv[8];
    if (bias) {
        float4 t0 = *(const float4*)(bias + ccol0);
        float4 t1 = *(const float4*)(bias + ccol0 + 4);
        bv[0]=t0.x; bv[1]=t0.y; bv[2]=t0.z; bv[3]=t0.w;
        bv[4]=t1.x; bv[5]=t1.y; bv[6]=t1.z; bv[7]=t1.w;
    } else {
        #pragma unroll
        for (int j = 0; j < 8; j++) bv[j] = 0.f;
    }
    #pragma unroll
    for (int i = 0; i < 8; i++) {
        float* crow = C + (size_t)(crow0 + i) * N + ccol0;
        float4 o0 = make_float4(acc[i][0]+bv[0], acc[i][1]+bv[1], acc[i][2]+bv[2], acc[i][3]+bv[3]);
        float4 o1 = make_float4(acc[i][4]+bv[4], acc[i][5]+bv[5], acc[i][6]+bv[6], acc[i][7]+bv[7]);
        *(float4*)crow       = o0;
        *(float4*)(crow + 4) = o1;
    }
}

// ---------------------------------------------------------------------------
// Flash attention, fp32, causal. One block per (b, h, 64-row q tile).
// Q/K read from g_qkv [row][3*1024] layout: q at +0, k at +1024, v at +2048,
// within-head dims contiguous (h*64 + d).
// Thread layout: 256 threads, tx=tid&15 ty=tid>>4.
// Scores: rows r=ty*4+i, cols c=tx+16*j  (interleaved cols -> conflict-free LDS)
// PV:     rows r=ty*4+i, cols d=tx*4+dd  (contiguous -> float4 V reads/ctx writes)
// ---------------------------------------------------------------------------
#define SQ 68   // padded stride for Qs/Ks/Ps (floats); 68*4B is 16B-aligned

#define FLASH_SMEM_FLOATS (64*SQ /*Q*/ + 64*SQ /*K*/ + 64*64 /*V*/ + 64*SQ /*P*/)
#define FLASH_SMEM_BYTES  (FLASH_SMEM_FLOATS * 4)

__global__ __launch_bounds__(256) void flash_attn(
    const float* __restrict__ qkv, float* __restrict__ ctx)
{
    extern __shared__ float sm[];
    float* Qs = sm;                 // [64][SQ]
    float* Ks = Qs + 64 * SQ;       // [64][SQ]
    float* Vs = Ks + 64 * SQ;       // [64][64]
    float* Ps = Vs + 64 * 64;       // [64][SQ]

    const int qt = blockIdx.x;      // q tile (0..31)
    const int h  = blockIdx.y;
    const int b  = blockIdx.z;
    const int tid = threadIdx.x;
    const int tx = tid & 15, ty = tid >> 4;
    const int q0 = qt * 64;
    const float scale = 0.125f;     // 1/sqrt(64)

    const float* qbase = qkv + (size_t)b * SEQ * QKV_N + (size_t)h * HDIM;
    const float* kbase = qbase + DMODEL;
    const float* vbase = qbase + 2 * DMODEL;

    // load Q tile [64][64]
    {
        const int rl = tid >> 4;          // 0..15
        const int c4 = (tid & 15) * 4;
        #pragma unroll
        for (int rr = 0; rr < 4; rr++) {
            int row = rl + rr * 16;
            float4 v = *(const float4*)(qbase + (size_t)(q0 + row) * QKV_N + c4);
            *(float4*)&Qs[row * SQ + c4] = v;
        }
    }

    float m_i[4], l_i[4], acc[4][4];
    #pragma unroll
    for (int i = 0; i < 4; i++) {
        m_i[i] = -INFINITY; l_i[i] = 0.f;
        #pragma unroll
        for (int j = 0; j < 4; j++) acc[i][j] = 0.f;
    }

    for (int kt = 0; kt <= qt; kt++) {
        __syncthreads();   // previous PV done; also orders Q-tile stores (1st iter)
        // load K,V tiles
        {
            const int rl = tid >> 4;
            const int c4 = (tid & 15) * 4;
            #pragma unroll
            for (int rr = 0; rr < 4; rr++) {
                int row = rl + rr * 16;
                size_t g = (size_t)(kt * 64 + row) * QKV_N + c4;
                float4 kv = *(const float4*)(kbase + g);
                float4 vv = *(const float4*)(vbase + g);
                *(float4*)&Ks[row * SQ + c4] = kv;
                *(float4*)&Vs[row * 64 + c4] = vv;
            }
        }
        __syncthreads();

        // scores S = Q K^T  (rows ty*4+i, cols tx+16j)
        float s[4][4];
        #pragma unroll
        for (int i = 0; i < 4; i++)
            #pragma unroll
            for (int j = 0; j < 4; j++) s[i][j] = 0.f;

        #pragma unroll
        for (int k0 = 0; k0 < 64; k0 += 4) {
            float4 qv[4], kv[4];
            #pragma unroll
            for (int i = 0; i < 4; i++)
                qv[i] = *(const float4*)&Qs[(ty * 4 + i) * SQ + k0];
            #pragma unroll
            for (int j = 0; j < 4; j++)
                kv[j] = *(const float4*)&Ks[(tx + 16 * j) * SQ + k0];
            #pragma unroll
            for (int i = 0; i < 4; i++)
                #pragma unroll
                for (int j = 0; j < 4; j++)
                    s[i][j] += qv[i].x * kv[j].x + qv[i].y * kv[j].y
                             + qv[i].z * kv[j].z + qv[i].w * kv[j].w;
        }

        // mask + scale + online softmax (row state replicated across 16 tx lanes)
        #pragma unroll
        for (int i = 0; i < 4; i++) {
            const int qi = q0 + ty * 4 + i;
            float rmax = -INFINITY;
            #pragma unroll
            for (int j = 0; j < 4; j++) {
                int ki = kt * 64 + tx + 16 * j;
                float v = (ki <= qi) ? s[i][j] * scale : -INFINITY;
                s[i][j] = v;
                rmax = fmaxf(rmax, v);
            }
            rmax = fmaxf(rmax, __shfl_xor_sync(0xffffffffu, rmax, 1));
            rmax = fmaxf(rmax, __shfl_xor_sync(0xffffffffu, rmax, 2));
            rmax = fmaxf(rmax, __shfl_xor_sync(0xffffffffu, rmax, 4));
            rmax = fmaxf(rmax, __shfl_xor_sync(0xffffffffu, rmax, 8));
            float mnew = fmaxf(m_i[i], rmax);          // always finite (col kt*64 unmasked)
            float corr = __expf(m_i[i] - mnew);        // 0 on first tile (-inf - finite)
            float rsum = 0.f;
            #pragma unroll
            for (int j = 0; j < 4; j++) {
                float p = __expf(s[i][j] - mnew);      // masked: exp(-inf)=0
                s[i][j] = p;
                rsum += p;
            }
            rsum += __shfl_xor_sync(0xffffffffu, rsum, 1);
            rsum += __shfl_xor_sync(0xffffffffu, rsum, 2);
            rsum += __shfl_xor_sync(0xffffffffu, rsum, 4);
            rsum += __shfl_xor_sync(0xffffffffu, rsum, 8);
            l_i[i] = l_i[i] * corr + rsum;
            m_i[i] = mnew;
            #pragma unroll
            for (int d = 0; d < 4; d++) acc[i][d] *= corr;
            // store P (scalar, conflict-free: banks = f(tx) distinct per instr)
            #pragma unroll
            for (int j = 0; j < 4; j++)
                Ps[(ty * 4 + i) * SQ + tx + 16 * j] = s[i][j];
        }
        __syncthreads();

        // ctx += P @ V   (rows ty*4+i, cols tx*4+dd)
        #pragma unroll
        for (int j0 = 0; j0 < 64; j0 += 4) {
            float4 pv[4], vv[4];
            #pragma unroll
            for (int i = 0; i < 4; i++)
                pv[i] = *(const float4*)&Ps[(ty * 4 + i) * SQ + j0];
            #pragma unroll
            for (int jj = 0; jj < 4; jj++)
                vv[jj] = *(const float4*)&Vs[(j0 + jj) * 64 + tx * 4];
            #pragma unroll
            for (int i = 0; i < 4; i++) {
                acc[i][0] += pv[i].x * vv[0].x + pv[i].y * vv[1].x + pv[i].z * vv[2].x + pv[i].w * vv[3].x;
                acc[i][1] += pv[i].x * vv[0].y + pv[i].y * vv[1].y + pv[i].z * vv[2].y + pv[i].w * vv[3].y;
                acc[i][2] += pv[i].x * vv[0].z + pv[i].y * vv[1].z + pv[i].z * vv[2].z + pv[i].w * vv[3].z;
                acc[i][3] += pv[i].x * vv[0].w + pv[i].y * vv[1].w + pv[i].z * vv[2].w + pv[i].w * vv[3].w;
            }
        }
    }

    // normalize + write ctx in [b*S+s][h*64+d] (== [B,S,D] row-major)
    #pragma unroll
    for (int i = 0; i < 4; i++) {
        float inv = 1.0f / l_i[i];
        float4 o = make_float4(acc[i][0] * inv, acc[i][1] * inv,
                               acc[i][2] * inv, acc[i][3] * inv);
        size_t row = (size_t)b * SEQ + q0 + ty * 4 + i;
        *(float4*)(ctx + row * DMODEL + h * HDIM + tx * 4) = o;
    }
}

// ---------------------------------------------------------------------------
extern "C" void kernel_launch(void* const* d_in, const int* in_sizes, int n_in,
                              void* d_out, int out_size)
{
    (void)in_sizes; (void)n_in; (void)out_size;
    const float* x     = (const float*)d_in[0];   // [2,2048,1024]
    const float* W_qkv = (const float*)d_in[1];   // [1024,3072]
    const float* b_qkv = (const float*)d_in[2];   // [3072]
    const float* W_out = (const float*)d_in[3];   // [1024,1024]
    float* out = (float*)d_out;                   // [2,2048,1024]

    float* qkv; cudaGetSymbolAddress((void**)&qkv, g_qkv);
    float* ctx; cudaGetSymbolAddress((void**)&ctx, g_ctx);

    cudaFuncSetAttribute(flash_attn, cudaFuncAttributeMaxDynamicSharedMemorySize,
                         FLASH_SMEM_BYTES);

    // 1) QKV projection: [4096,1024] @ [1024,3072] + bias
    sgemm128<<<dim3(QKV_N / 128, ROWS / 128), 256>>>(x, W_qkv, b_qkv, qkv,
                                                     ROWS, QKV_N, DMODEL);
    // 2) causal flash attention
    flash_attn<<<dim3(SEQ / 64, NHEAD, BATCH), 256, FLASH_SMEM_BYTES>>>(qkv, ctx);
    // 3) output projection: [4096,1024] @ [1024,1024]
    sgemm128<<<dim3(DMODEL / 128, ROWS / 128), 256>>>(ctx, W_out, nullptr, out,
                                                      ROWS, DMODEL, DMODEL);
}

// round 3
// speedup vs baseline: 1.4393x; 1.4393x over previous
#include <cuda_runtime.h>
#include <cuda_bf16.h>
#include <math.h>
#include <stdint.h>

// Problem constants
#define BATCH 2
#define SEQ   2048
#define DMODEL 1024
#define NHEAD 16
#define HDIM  64
#define ROWS  (BATCH*SEQ)          // 4096
#define QKV_N (3*DMODEL)           // 3072

// ---------------------------------------------------------------------------
// Device scratch (no cudaMalloc allowed)
// ---------------------------------------------------------------------------
__device__ float g_qkv[(size_t)ROWS * QKV_N];            // 48 MB fp32 qkv
__device__ float g_ctx[(size_t)ROWS * DMODEL];           // 16 MB fp32 ctx
__device__ __nv_bfloat16 g_xhi[(size_t)ROWS * DMODEL];
__device__ __nv_bfloat16 g_xlo[(size_t)ROWS * DMODEL];
__device__ __nv_bfloat16 g_wqh[(size_t)QKV_N * DMODEL];  // W_qkv^T [3072][1024]
__device__ __nv_bfloat16 g_wql[(size_t)QKV_N * DMODEL];
__device__ __nv_bfloat16 g_woh[(size_t)DMODEL * DMODEL]; // W_out^T [1024][1024]
__device__ __nv_bfloat16 g_wol[(size_t)DMODEL * DMODEL];
__device__ __nv_bfloat16 g_chi[(size_t)ROWS * DMODEL];
__device__ __nv_bfloat16 g_clo[(size_t)ROWS * DMODEL];

// ---------------------------------------------------------------------------
// PTX helpers (sm_80-compatible path only: cp.async + ldmatrix + mma.sync)
// ---------------------------------------------------------------------------
__device__ __forceinline__ uint32_t smem_u32(const void* p) {
    uint32_t a;
    asm("{ .reg .u64 t; cvta.to.shared.u64 t, %1; cvt.u32.u64 %0, t; }" : "=r"(a) : "l"(p));
    return a;
}
#define CP16(sm, gm) asm volatile("cp.async.cg.shared.global [%0], [%1], 16;" :: "r"(sm), "l"(gm))
#define CP_COMMIT()  asm volatile("cp.async.commit_group;" ::: "memory")
#define CP_WAIT1()   asm volatile("cp.async.wait_group 1;" ::: "memory")
#define CP_WAIT0()   asm volatile("cp.async.wait_group 0;" ::: "memory")

__device__ __forceinline__ void ldsm4(uint32_t* r, uint32_t addr) {
    asm volatile("ldmatrix.sync.aligned.m8n8.x4.shared.b16 {%0,%1,%2,%3}, [%4];"
                 : "=r"(r[0]), "=r"(r[1]), "=r"(r[2]), "=r"(r[3]) : "r"(addr));
}
__device__ __forceinline__ void mma16816(float* c, const uint32_t* a, const uint32_t* b) {
    asm volatile(
        "mma.sync.aligned.m16n8k16.row.col.f32.bf16.bf16.f32 "
        "{%0,%1,%2,%3}, {%4,%5,%6,%7}, {%8,%9}, {%0,%1,%2,%3};"
        : "+f"(c[0]), "+f"(c[1]), "+f"(c[2]), "+f"(c[3])
        : "r"(a[0]), "r"(a[1]), "r"(a[2]), "r"(a[3]), "r"(b[0]), "r"(b[1]));
}

// ---------------------------------------------------------------------------
// Pre-pass: fp32 -> (bf16 hi, bf16 lo) elementwise (vectorized by 4)
// ---------------------------------------------------------------------------
__global__ __launch_bounds__(256) void decomp_kernel(
    const float* __restrict__ s, __nv_bfloat16* __restrict__ hi,
    __nv_bfloat16* __restrict__ lo, int n4)
{
    int i = blockIdx.x * 256 + threadIdx.x;
    if (i >= n4) return;
    float4 v = ((const float4*)s)[i];
    float vv[4] = {v.x, v.y, v.z, v.w};
    __align__(8) __nv_bfloat16 h[4], l[4];
    #pragma unroll
    for (int j = 0; j < 4; j++) {
        h[j] = __float2bfloat16(vv[j]);
        l[j] = __float2bfloat16(vv[j] - __bfloat162float(h[j]));
    }
    *(uint2*)(hi + 4 * (size_t)i) = *(uint2*)h;
    *(uint2*)(lo + 4 * (size_t)i) = *(uint2*)l;
}

// Transpose + decompose: W [K][N] fp32 -> Wt hi/lo [N][K] bf16
__global__ __launch_bounds__(256) void tdecomp_kernel(
    const float* __restrict__ W, __nv_bfloat16* __restrict__ hi,
    __nv_bfloat16* __restrict__ lo, int K, int N)
{
    __shared__ float t[32][33];
    const int tx = threadIdx.x, ty = threadIdx.y;   // 32 x 8
    const int n0 = blockIdx.x * 32, k0 = blockIdx.y * 32;
    #pragma unroll
    for (int i = 0; i < 4; i++)
        t[ty + i * 8][tx] = W[(size_t)(k0 + ty + i * 8) * N + n0 + tx];
    __syncthreads();
    #pragma unroll
    for (int i = 0; i < 4; i++) {
        float v = t[tx][ty + i * 8];
        __nv_bfloat16 h = __float2bfloat16(v);
        __nv_bfloat16 l = __float2bfloat16(v - __bfloat162float(h));
        size_t o = (size_t)(n0 + ty + i * 8) * K + k0 + tx;
        hi[o] = h; lo[o] = l;
    }
}

// ---------------------------------------------------------------------------
// Tensor-core GEMM via mma.sync (HMMA), bf16 3-MMA split (~fp32 accuracy):
//   C[M,N] = A @ B (+bias),  A = (Ah+Al) bf16 [M][K] row-major,
//   B = (Bh+Bl) bf16 [N][K] row-major (i.e. col-major K x N).
// 128x128 CTA, BK=32, 8 warps (2x4), warp tile 64x32, cp.async 3-stage ring.
// Smem rows padded to 40 bf16 (80 B): (r*5) mod 8 is a permutation ->
// ldmatrix and cp.async stores are phase-conflict-free.
// ---------------------------------------------------------------------------
#define GK 32                 // BK
#define GROW 80               // smem row stride bytes (40 bf16)
#define GSUB (128 * GROW)     // 10240 B per sub-matrix
#define GSTAGE (4 * GSUB)     // Ah|Al|Bh|Bl = 40960 B
#define GNBUF 3
#define GM_DYN_BYTES (GNBUF * GSTAGE + 256)

__device__ __forceinline__ void gm_load_stage(
    uint32_t buf, const __nv_bfloat16* gah, const __nv_bfloat16* gal,
    const __nv_bfloat16* gbh, const __nv_bfloat16* gbl, int K, int tid)
{
    // 512 16B-chunks per sub-matrix (128 rows x 4 chunks); 256 threads x 2
    #pragma unroll
    for (int i = 0; i < 2; i++) {
        int c = i * 256 + tid;
        int row = c >> 2, col = c & 3;
        uint32_t so = (uint32_t)(row * GROW + col * 16);
        size_t g = (size_t)row * K + (size_t)col * 8;
        CP16(buf + so,            gah + g);
        CP16(buf + GSUB + so,     gal + g);
        CP16(buf + 2 * GSUB + so, gbh + g);
        CP16(buf + 3 * GSUB + so, gbl + g);
    }
}

__global__ __launch_bounds__(256, 1) void gemm_hmma_x3(
    const __nv_bfloat16* __restrict__ Ah, const __nv_bfloat16* __restrict__ Al,
    const __nv_bfloat16* __restrict__ Bh, const __nv_bfloat16* __restrict__ Bl,
    const float* __restrict__ bias, float* __restrict__ C,
    int M, int N, int K)
{
    extern __shared__ __align__(128) char dynsm[];
    const uint32_t smbase = smem_u32(dynsm);

    const int tid = threadIdx.x;
    const int wid = tid >> 5, lane = tid & 31;
    const int wr = wid >> 2, wc = wid & 3;          // warp grid 2 x 4
    const int m0 = blockIdx.y * 128, n0 = blockIdx.x * 128;

    const __nv_bfloat16* ah0 = Ah + (size_t)m0 * K;
    const __nv_bfloat16* al0 = Al + (size_t)m0 * K;
    const __nv_bfloat16* bh0 = Bh + (size_t)n0 * K;
    const __nv_bfloat16* bl0 = Bl + (size_t)n0 * K;

    // per-lane ldmatrix base offsets (within a stage buffer)
    // A tile i (16 rows): rows wr*64 + i*16 + (lane%16); k-half sel: +16B if lane>=16
    const uint32_t a_off = (uint32_t)((wr * 64 + (lane & 15)) * GROW + (lane >> 4) * 16);
    // B pair p (16 n-rows): rows wc*32 + p*16 + (lane/16)*8 + (lane%8); k-half ((lane%16)/8)
    const uint32_t b_off = (uint32_t)((wc * 32 + (lane >> 4) * 8 + (lane & 7)) * GROW
                                      + (((lane & 15) >> 3) * 16));

    float acc[4][4][4];
    #pragma unroll
    for (int i = 0; i < 4; i++)
        #pragma unroll
        for (int j = 0; j < 4; j++)
            #pragma unroll
            for (int r = 0; r < 4; r++) acc[i][j][r] = 0.f;

    const int NS = K / GK;   // 32 for K=1024

    gm_load_stage(smbase, ah0, al0, bh0, bl0, K, tid);
    CP_COMMIT();
    gm_load_stage(smbase + GSTAGE, ah0 + GK, al0 + GK, bh0 + GK, bl0 + GK, K, tid);
    CP_COMMIT();

    for (int s = 0; s < NS; s++) {
        if (s == NS - 1) { CP_WAIT0(); } else { CP_WAIT1(); }
        __syncthreads();

        int t = s + 2;
        if (t < NS) {
            gm_load_stage(smbase + (uint32_t)(t % GNBUF) * GSTAGE,
                          ah0 + (size_t)t * GK, al0 + (size_t)t * GK,
                          bh0 + (size_t)t * GK, bl0 + (size_t)t * GK, K, tid);
            CP_COMMIT();
        }

        const uint32_t sb = smbase + (uint32_t)(s % GNBUF) * GSTAGE;
        #pragma unroll
        for (int kk = 0; kk < 2; kk++) {
            uint32_t ah[4][4], al[4][4], bh[2][4], bl[2][4];
            const uint32_t ko = (uint32_t)(kk * 32);
            #pragma unroll
            for (int i = 0; i < 4; i++) {
                ldsm4(ah[i], sb + a_off + (uint32_t)(i * 16 * GROW) + ko);
                ldsm4(al[i], sb + GSUB + a_off + (uint32_t)(i * 16 * GROW) + ko);
            }
            #pragma unroll
            for (int p = 0; p < 2; p++) {
                ldsm4(bh[p], sb + 2 * GSUB + b_off + (uint32_t)(p * 16 * GROW) + ko);
                ldsm4(bl[p], sb + 3 * GSUB + b_off + (uint32_t)(p * 16 * GROW) + ko);
            }
            #pragma unroll
            for (int i = 0; i < 4; i++)
                #pragma unroll
                for (int j = 0; j < 4; j++) {
                    const uint32_t* bhj = &bh[j >> 1][(j & 1) * 2];
                    const uint32_t* blj = &bl[j >> 1][(j & 1) * 2];
                    mma16816(acc[i][j], ah[i], bhj);
                    mma16816(acc[i][j], ah[i], blj);
                    mma16816(acc[i][j], al[i], bhj);
                }
        }
        __syncthreads();
    }

    // epilogue
    const int er = m0 + wr * 64 + (lane >> 2);
    const int ec = n0 + wc * 32 + 2 * (lane & 3);
    #pragma unroll
    for (int i = 0; i < 4; i++) {
        #pragma unroll
        for (int j = 0; j < 4; j++) {
            int r = er + i * 16;
            int c = ec + j * 8;
            float b0 = bias ? bias[c] : 0.f;
            float b1 = bias ? bias[c + 1] : 0.f;
            *(float2*)(C + (size_t)r * N + c) =
                make_float2(acc[i][j][0] + b0, acc[i][j][1] + b1);
            *(float2*)(C + (size_t)(r + 8) * N + c) =
                make_float2(acc[i][j][2] + b0, acc[i][j][3] + b1);
        }
    }
}

// ---------------------------------------------------------------------------
// Flash attention, fp32, causal (validated in R1)
// ---------------------------------------------------------------------------
#define SQ 68
#define FLASH_SMEM_FLOATS (64*SQ + 64*SQ + 64*64 + 64*SQ)
#define FLASH_SMEM_BYTES  (FLASH_SMEM_FLOATS * 4)

__global__ __launch_bounds__(256) void flash_attn(
    const float* __restrict__ qkv, float* __restrict__ ctx)
{
    extern __shared__ float sm[];
    float* Qs = sm;
    float* Ks = Qs + 64 * SQ;
    float* Vs = Ks + 64 * SQ;
    float* Ps = Vs + 64 * 64;

    const int qt = gridDim.x - 1 - blockIdx.x;   // longest tiles first
    const int h  = blockIdx.y;
    const int b  = blockIdx.z;
    const int tid = threadIdx.x;
    const int tx = tid & 15, ty = tid >> 4;
    const int q0 = qt * 64;
    const float scale = 0.125f;

    const float* qbase = qkv + (size_t)b * SEQ * QKV_N + (size_t)h * HDIM;
    const float* kbase = qbase + DMODEL;
    const float* vbase = qbase + 2 * DMODEL;

    {
        const int rl = tid >> 4;
        const int c4 = (tid & 15) * 4;
        #pragma unroll
        for (int rr = 0; rr < 4; rr++) {
            int row = rl + rr * 16;
            float4 v = *(const float4*)(qbase + (size_t)(q0 + row) * QKV_N + c4);
            *(float4*)&Qs[row * SQ + c4] = v;
        }
    }

    float m_i[4], l_i[4], acc[4][4];
    #pragma unroll
    for (int i = 0; i < 4; i++) {
        m_i[i] = -INFINITY; l_i[i] = 0.f;
        #pragma unroll
        for (int j = 0; j < 4; j++) acc[i][j] = 0.f;
    }

    for (int kt = 0; kt <= qt; kt++) {
        __syncthreads();
        {
            const int rl = tid >> 4;
            const int c4 = (tid & 15) * 4;
            #pragma unroll
            for (int rr = 0; rr < 4; rr++) {
                int row = rl + rr * 16;
                size_t g = (size_t)(kt * 64 + row) * QKV_N + c4;
                float4 kv = *(const float4*)(kbase + g);
                float4 vv = *(const float4*)(vbase + g);
                *(float4*)&Ks[row * SQ + c4] = kv;
                *(float4*)&Vs[row * 64 + c4] = vv;
            }
        }
        __syncthreads();

        float s[4][4];
        #pragma unroll
        for (int i = 0; i < 4; i++)
            #pragma unroll
            for (int j = 0; j < 4; j++) s[i][j] = 0.f;

        #pragma unroll
        for (int k0 = 0; k0 < 64; k0 += 4) {
            float4 qv[4], kv[4];
            #pragma unroll
            for (int i = 0; i < 4; i++)
                qv[i] = *(const float4*)&Qs[(ty * 4 + i) * SQ + k0];
            #pragma unroll
            for (int j = 0; j < 4; j++)
                kv[j] = *(const float4*)&Ks[(tx + 16 * j) * SQ + k0];
            #pragma unroll
            for (int i = 0; i < 4; i++)
                #pragma unroll
                for (int j = 0; j < 4; j++)
                    s[i][j] += qv[i].x * kv[j].x + qv[i].y * kv[j].y
                             + qv[i].z * kv[j].z + qv[i].w * kv[j].w;
        }

        #pragma unroll
        for (int i = 0; i < 4; i++) {
            const int qi = q0 + ty * 4 + i;
            float rmax = -INFINITY;
            #pragma unroll
            for (int j = 0; j < 4; j++) {
                int ki = kt * 64 + tx + 16 * j;
                float v = (ki <= qi) ? s[i][j] * scale : -INFINITY;
                s[i][j] = v;
                rmax = fmaxf(rmax, v);
            }
            rmax = fmaxf(rmax, __shfl_xor_sync(0xffffffffu, rmax, 1));
            rmax = fmaxf(rmax, __shfl_xor_sync(0xffffffffu, rmax, 2));
            rmax = fmaxf(rmax, __shfl_xor_sync(0xffffffffu, rmax, 4));
            rmax = fmaxf(rmax, __shfl_xor_sync(0xffffffffu, rmax, 8));
            float mnew = fmaxf(m_i[i], rmax);
            float corr = __expf(m_i[i] - mnew);
            float rsum = 0.f;
            #pragma unroll
            for (int j = 0; j < 4; j++) {
                float p = __expf(s[i][j] - mnew);
                s[i][j] = p;
                rsum += p;
            }
            rsum += __shfl_xor_sync(0xffffffffu, rsum, 1);
            rsum += __shfl_xor_sync(0xffffffffu, rsum, 2);
            rsum += __shfl_xor_sync(0xffffffffu, rsum, 4);
            rsum += __shfl_xor_sync(0xffffffffu, rsum, 8);
            l_i[i] = l_i[i] * corr + rsum;
            m_i[i] = mnew;
            #pragma unroll
            for (int d = 0; d < 4; d++) acc[i][d] *= corr;
            #pragma unroll
            for (int j = 0; j < 4; j++)
                Ps[(ty * 4 + i) * SQ + tx + 16 * j] = s[i][j];
        }
        __syncthreads();

        #pragma unroll
        for (int j0 = 0; j0 < 64; j0 += 4) {
            float4 pv[4], vv[4];
            #pragma unroll
            for (int i = 0; i < 4; i++)
                pv[i] = *(const float4*)&Ps[(ty * 4 + i) * SQ + j0];
            #pragma unroll
            for (int jj = 0; jj < 4; jj++)
                vv[jj] = *(const float4*)&Vs[(j0 + jj) * 64 + tx * 4];
            #pragma unroll
            for (int i = 0; i < 4; i++) {
                acc[i][0] += pv[i].x * vv[0].x + pv[i].y * vv[1].x + pv[i].z * vv[2].x + pv[i].w * vv[3].x;
                acc[i][1] += pv[i].x * vv[0].y + pv[i].y * vv[1].y + pv[i].z * vv[2].y + pv[i].w * vv[3].y;
                acc[i][2] += pv[i].x * vv[0].z + pv[i].y * vv[1].z + pv[i].z * vv[2].z + pv[i].w * vv[3].z;
                acc[i][3] += pv[i].x * vv[0].w + pv[i].y * vv[1].w + pv[i].z * vv[2].w + pv[i].w * vv[3].w;
            }
        }
    }

    #pragma unroll
    for (int i = 0; i < 4; i++) {
        float inv = 1.0f / l_i[i];
        float4 o = make_float4(acc[i][0] * inv, acc[i][1] * inv,
                               acc[i][2] * inv, acc[i][3] * inv);
        size_t row = (size_t)b * SEQ + q0 + ty * 4 + i;
        *(float4*)(ctx + row * DMODEL + h * HDIM + tx * 4) = o;
    }
}

// ---------------------------------------------------------------------------
extern "C" void kernel_launch(void* const* d_in, const int* in_sizes, int n_in,
                              void* d_out, int out_size)
{
    (void)in_sizes; (void)n_in; (void)out_size;
    const float* x     = (const float*)d_in[0];
    const float* W_qkv = (const float*)d_in[1];
    const float* b_qkv = (const float*)d_in[2];
    const float* W_out = (const float*)d_in[3];
    float* out = (float*)d_out;

    float* qkv; cudaGetSymbolAddress((void**)&qkv, g_qkv);
    float* ctx; cudaGetSymbolAddress((void**)&ctx, g_ctx);
    __nv_bfloat16 *xhi, *xlo, *wqh, *wql, *woh, *wol, *chi, *clo;
    cudaGetSymbolAddress((void**)&xhi, g_xhi);
    cudaGetSymbolAddress((void**)&xlo, g_xlo);
    cudaGetSymbolAddress((void**)&wqh, g_wqh);
    cudaGetSymbolAddress((void**)&wql, g_wql);
    cudaGetSymbolAddress((void**)&woh, g_woh);
    cudaGetSymbolAddress((void**)&wol, g_wol);
    cudaGetSymbolAddress((void**)&chi, g_chi);
    cudaGetSymbolAddress((void**)&clo, g_clo);

    cudaFuncSetAttribute(flash_attn, cudaFuncAttributeMaxDynamicSharedMemorySize,
                         FLASH_SMEM_BYTES);
    cudaFuncSetAttribute(gemm_hmma_x3, cudaFuncAttributeMaxDynamicSharedMemorySize,
                         GM_DYN_BYTES);

    // pre-pass: decompose x, W_qkv^T, W_out^T into bf16 hi/lo
    decomp_kernel<<<(ROWS * DMODEL / 4 + 255) / 256, 256>>>(x, xhi, xlo, ROWS * DMODEL / 4);
    tdecomp_kernel<<<dim3(QKV_N / 32, DMODEL / 32), dim3(32, 8)>>>(W_qkv, wqh, wql, DMODEL, QKV_N);
    tdecomp_kernel<<<dim3(DMODEL / 32, DMODEL / 32), dim3(32, 8)>>>(W_out, woh, wol, DMODEL, DMODEL);

    // 1) QKV projection (tensor cores via mma.sync)
    gemm_hmma_x3<<<dim3(QKV_N / 128, ROWS / 128), 256, GM_DYN_BYTES>>>(
        xhi, xlo, wqh, wql, b_qkv, qkv, ROWS, QKV_N, DMODEL);

    // 2) causal flash attention (fp32 SIMT)
    flash_attn<<<dim3(SEQ / 64, NHEAD, BATCH), 256, FLASH_SMEM_BYTES>>>(qkv, ctx);

    // 3) output projection (tensor cores)
    decomp_kernel<<<(ROWS * DMODEL / 4 + 255) / 256, 256>>>(ctx, chi, clo, ROWS * DMODEL / 4);
    gemm_hmma_x3<<<dim3(DMODEL / 128, ROWS / 128), 256, GM_DYN_BYTES>>>(
        chi, clo, woh, wol, nullptr, out, ROWS, DMODEL, DMODEL);
}

// round 4
// speedup vs baseline: 2.3612x; 1.6405x over previous
#include <cuda_runtime.h>
#include <cuda_bf16.h>
#include <math.h>
#include <stdint.h>

#define BATCH 2
#define SEQ   2048
#define DMODEL 1024
#define NHEAD 16
#define HDIM  64
#define ROWS  (BATCH*SEQ)          // 4096
#define QKV_N (3*DMODEL)           // 3072

typedef __nv_bfloat16 bf;

// ---------------------------------------------------------------------------
// Device scratch
// ---------------------------------------------------------------------------
__device__ bf g_xhi[(size_t)ROWS * DMODEL];
__device__ bf g_xlo[(size_t)ROWS * DMODEL];
__device__ bf g_wqh[(size_t)QKV_N * DMODEL];   // W_qkv^T [3072][1024]
__device__ bf g_wql[(size_t)QKV_N * DMODEL];
__device__ bf g_woh[(size_t)DMODEL * DMODEL];  // W_out^T [1024][1024]
__device__ bf g_wol[(size_t)DMODEL * DMODEL];
__device__ bf g_chi[(size_t)ROWS * DMODEL];    // ctx hi/lo [row][1024]
__device__ bf g_clo[(size_t)ROWS * DMODEL];
// q/k/v split, layout [b][h][s][d]
__device__ bf g_qh[(size_t)BATCH * NHEAD * SEQ * HDIM];
__device__ bf g_ql[(size_t)BATCH * NHEAD * SEQ * HDIM];
__device__ bf g_kh[(size_t)BATCH * NHEAD * SEQ * HDIM];
__device__ bf g_kl[(size_t)BATCH * NHEAD * SEQ * HDIM];
__device__ bf g_vh[(size_t)BATCH * NHEAD * SEQ * HDIM];
__device__ bf g_vl[(size_t)BATCH * NHEAD * SEQ * HDIM];

// ---------------------------------------------------------------------------
// PTX helpers
// ---------------------------------------------------------------------------
__device__ __forceinline__ uint32_t smem_u32(const void* p) {
    uint32_t a;
    asm("{ .reg .u64 t; cvta.to.shared.u64 t, %1; cvt.u32.u64 %0, t; }" : "=r"(a) : "l"(p));
    return a;
}
#define CP16(sm, gm) asm volatile("cp.async.cg.shared.global [%0], [%1], 16;" :: "r"(sm), "l"(gm))
#define CP_COMMIT()  asm volatile("cp.async.commit_group;" ::: "memory")
#define CP_WAIT1()   asm volatile("cp.async.wait_group 1;" ::: "memory")
#define CP_WAIT0()   asm volatile("cp.async.wait_group 0;" ::: "memory")

__device__ __forceinline__ void ldsm4(uint32_t* r, uint32_t addr) {
    asm volatile("ldmatrix.sync.aligned.m8n8.x4.shared.b16 {%0,%1,%2,%3}, [%4];"
                 : "=r"(r[0]), "=r"(r[1]), "=r"(r[2]), "=r"(r[3]) : "r"(addr));
}
__device__ __forceinline__ void ldsm4t(uint32_t* r, uint32_t addr) {
    asm volatile("ldmatrix.sync.aligned.m8n8.x4.trans.shared.b16 {%0,%1,%2,%3}, [%4];"
                 : "=r"(r[0]), "=r"(r[1]), "=r"(r[2]), "=r"(r[3]) : "r"(addr));
}
__device__ __forceinline__ void mma16816(float* c, const uint32_t* a, const uint32_t* b) {
    asm volatile(
        "mma.sync.aligned.m16n8k16.row.col.f32.bf16.bf16.f32 "
        "{%0,%1,%2,%3}, {%4,%5,%6,%7}, {%8,%9}, {%0,%1,%2,%3};"
        : "+f"(c[0]), "+f"(c[1]), "+f"(c[2]), "+f"(c[3])
        : "r"(a[0]), "r"(a[1]), "r"(a[2]), "r"(a[3]), "r"(b[0]), "r"(b[1]));
}
__device__ __forceinline__ uint32_t packbf(float x, float y) {
    __nv_bfloat162 t = __float22bfloat162_rn(make_float2(x, y));  // x -> low half
    return *(uint32_t*)&t;
}
// split (x,y) into bf16 hi pair + bf16 lo (residual) pair
__device__ __forceinline__ void split2(float x, float y, uint32_t& h, uint32_t& l) {
    h = packbf(x, y);
    float hx = __uint_as_float(h << 16);
    float hy = __uint_as_float(h & 0xffff0000u);
    l = packbf(x - hx, y - hy);
}

// ---------------------------------------------------------------------------
// Pre-pass: fp32 -> (bf16 hi, bf16 lo) elementwise (x only)
// ---------------------------------------------------------------------------
__global__ __launch_bounds__(256) void decomp_kernel(
    const float* __restrict__ s, bf* __restrict__ hi, bf* __restrict__ lo, int n4)
{
    int i = blockIdx.x * 256 + threadIdx.x;
    if (i >= n4) return;
    float4 v = ((const float4*)s)[i];
    uint32_t h0, l0, h1, l1;
    split2(v.x, v.y, h0, l0);
    split2(v.z, v.w, h1, l1);
    uint2 hh = make_uint2(h0, h1), ll = make_uint2(l0, l1);
    *(uint2*)(hi + 4 * (size_t)i) = hh;
    *(uint2*)(lo + 4 * (size_t)i) = ll;
}

// Transpose + decompose: W [K][N] fp32 -> Wt hi/lo [N][K] bf16
__global__ __launch_bounds__(256) void tdecomp_kernel(
    const float* __restrict__ W, bf* __restrict__ hi, bf* __restrict__ lo, int K, int N)
{
    __shared__ float t[32][33];
    const int tx = threadIdx.x, ty = threadIdx.y;   // 32 x 8
    const int n0 = blockIdx.x * 32, k0 = blockIdx.y * 32;
    #pragma unroll
    for (int i = 0; i < 4; i++)
        t[ty + i * 8][tx] = W[(size_t)(k0 + ty + i * 8) * N + n0 + tx];
    __syncthreads();
    #pragma unroll
    for (int i = 0; i < 4; i++) {
        float v = t[tx][ty + i * 8];
        bf h = __float2bfloat16(v);
        bf l = __float2bfloat16(v - __bfloat162float(h));
        size_t o = (size_t)(n0 + ty + i * 8) * K + k0 + tx;
        hi[o] = h; lo[o] = l;
    }
}

// ---------------------------------------------------------------------------
// Tensor-core GEMM via mma.sync, bf16 3-MMA split. EPI=0: fp32 C (no bias).
// EPI=1: fused QKV epilogue -> qh/ql/kh/kl/vh/vl [b][h][s][d], bias added,
//        q scaled by 1/sqrt(Hd).
// ---------------------------------------------------------------------------
#define GK 32
#define GROW 80
#define GSUB (128 * GROW)
#define GSTAGE (4 * GSUB)
#define GNBUF 3
#define GM_DYN_BYTES (GNBUF * GSTAGE + 256)

__device__ __forceinline__ void gm_load_stage(
    uint32_t buf, const bf* gah, const bf* gal, const bf* gbh, const bf* gbl,
    int K, int tid)
{
    #pragma unroll
    for (int i = 0; i < 2; i++) {
        int c = i * 256 + tid;
        int row = c >> 2, col = c & 3;
        uint32_t so = (uint32_t)(row * GROW + col * 16);
        size_t g = (size_t)row * K + (size_t)col * 8;
        CP16(buf + so,            gah + g);
        CP16(buf + GSUB + so,     gal + g);
        CP16(buf + 2 * GSUB + so, gbh + g);
        CP16(buf + 3 * GSUB + so, gbl + g);
    }
}

template<int EPI>
__global__ __launch_bounds__(256, 1) void gemm_hmma_x3(
    const bf* __restrict__ Ah, const bf* __restrict__ Al,
    const bf* __restrict__ Bh, const bf* __restrict__ Bl,
    const float* __restrict__ bias, float* __restrict__ C,
    bf* __restrict__ oqh, bf* __restrict__ oql,
    bf* __restrict__ okh, bf* __restrict__ okl,
    bf* __restrict__ ovh, bf* __restrict__ ovl,
    int M, int N, int K)
{
    extern __shared__ __align__(128) char dynsm[];
    const uint32_t smbase = smem_u32(dynsm);

    const int tid = threadIdx.x;
    const int wid = tid >> 5, lane = tid & 31;
    const int wr = wid >> 2, wc = wid & 3;
    const int m0 = blockIdx.y * 128, n0 = blockIdx.x * 128;

    const bf* ah0 = Ah + (size_t)m0 * K;
    const bf* al0 = Al + (size_t)m0 * K;
    const bf* bh0 = Bh + (size_t)n0 * K;
    const bf* bl0 = Bl + (size_t)n0 * K;

    const uint32_t a_off = (uint32_t)((wr * 64 + (lane & 15)) * GROW + (lane >> 4) * 16);
    const uint32_t b_off = (uint32_t)((wc * 32 + (lane >> 4) * 8 + (lane & 7)) * GROW
                                      + (((lane & 15) >> 3) * 16));

    float acc[4][4][4];
    #pragma unroll
    for (int i = 0; i < 4; i++)
        #pragma unroll
        for (int j = 0; j < 4; j++)
            #pragma unroll
            for (int r = 0; r < 4; r++) acc[i][j][r] = 0.f;

    const int NS = K / GK;

    gm_load_stage(smbase, ah0, al0, bh0, bl0, K, tid);
    CP_COMMIT();
    gm_load_stage(smbase + GSTAGE, ah0 + GK, al0 + GK, bh0 + GK, bl0 + GK, K, tid);
    CP_COMMIT();

    for (int s = 0; s < NS; s++) {
        if (s == NS - 1) { CP_WAIT0(); } else { CP_WAIT1(); }
        __syncthreads();

        int t = s + 2;
        if (t < NS) {
            gm_load_stage(smbase + (uint32_t)(t % GNBUF) * GSTAGE,
                          ah0 + (size_t)t * GK, al0 + (size_t)t * GK,
                          bh0 + (size_t)t * GK, bl0 + (size_t)t * GK, K, tid);
            CP_COMMIT();
        }

        const uint32_t sb = smbase + (uint32_t)(s % GNBUF) * GSTAGE;
        #pragma unroll
        for (int kk = 0; kk < 2; kk++) {
            uint32_t ah[4][4], al_[4][4], bh[2][4], bl[2][4];
            const uint32_t ko = (uint32_t)(kk * 32);
            #pragma unroll
            for (int i = 0; i < 4; i++) {
                ldsm4(ah[i],  sb + a_off + (uint32_t)(i * 16 * GROW) + ko);
                ldsm4(al_[i], sb + GSUB + a_off + (uint32_t)(i * 16 * GROW) + ko);
            }
            #pragma unroll
            for (int p = 0; p < 2; p++) {
                ldsm4(bh[p], sb + 2 * GSUB + b_off + (uint32_t)(p * 16 * GROW) + ko);
                ldsm4(bl[p], sb + 3 * GSUB + b_off + (uint32_t)(p * 16 * GROW) + ko);
            }
            #pragma unroll
            for (int i = 0; i < 4; i++)
                #pragma unroll
                for (int j = 0; j < 4; j++) {
                    const uint32_t* bhj = &bh[j >> 1][(j & 1) * 2];
                    const uint32_t* blj = &bl[j >> 1][(j & 1) * 2];
                    mma16816(acc[i][j], ah[i], bhj);
                    mma16816(acc[i][j], ah[i], blj);
                    mma16816(acc[i][j], al_[i], bhj);
                }
        }
        __syncthreads();
    }

    const int er = m0 + wr * 64 + (lane >> 2);
    const int ec = n0 + wc * 32 + 2 * (lane & 3);

    if (EPI == 0) {
        #pragma unroll
        for (int i = 0; i < 4; i++)
            #pragma unroll
            for (int j = 0; j < 4; j++) {
                int r = er + i * 16, c = ec + j * 8;
                *(float2*)(C + (size_t)r * N + c) =
                    make_float2(acc[i][j][0], acc[i][j][1]);
                *(float2*)(C + (size_t)(r + 8) * N + c) =
                    make_float2(acc[i][j][2], acc[i][j][3]);
            }
    } else {
        // part is constant per CTA (128-col blocks never straddle 1024 bounds)
        const int part = ec >> 10;
        bf *dh, *dl;
        if (part == 0)      { dh = oqh; dl = oql; }
        else if (part == 1) { dh = okh; dl = okl; }
        else                { dh = ovh; dl = ovl; }
        const float sc = (part == 0) ? 0.125f : 1.0f;   // fold attention scale into q
        #pragma unroll
        for (int i = 0; i < 4; i++)
            #pragma unroll
            for (int j = 0; j < 4; j++) {
                int r = er + i * 16, c = ec + j * 8;
                int hh = (c >> 6) & 15, d = c & 63;
                float b0 = bias[c], b1 = bias[c + 1];
                uint32_t ph, pl;
                split2((acc[i][j][0] + b0) * sc, (acc[i][j][1] + b1) * sc, ph, pl);
                size_t off = (((size_t)(r >> 11) * NHEAD + hh) * SEQ + (r & 2047)) * HDIM + d;
                *(uint32_t*)(dh + off) = ph;
                *(uint32_t*)(dl + off) = pl;
                split2((acc[i][j][2] + b0) * sc, (acc[i][j][3] + b1) * sc, ph, pl);
                int r2 = r + 8;
                off = (((size_t)(r2 >> 11) * NHEAD + hh) * SEQ + (r2 & 2047)) * HDIM + d;
                *(uint32_t*)(dh + off) = ph;
                *(uint32_t*)(dl + off) = pl;
            }
    }
}

// ---------------------------------------------------------------------------
// HMMA flash attention, causal, bf16 3-MMA split on QK^T and PV.
// CTA = 128 q rows x one (b,h); 8 warps, warp = 16 q x 64 keys.
// K/V tiles 64 keys, 3-stage cp.async ring. Scale pre-folded into q.
// Writes ctx directly as bf16 hi/lo [row][1024].
// ---------------------------------------------------------------------------
#define AROW 144                         // smem row stride bytes (64 bf16 data)
#define AQ_BYTES (128 * AROW)            // 18432 per q array
#define AKV_BYTES (64 * AROW)            // 9216 per k/v array
#define AST (4 * AKV_BYTES)              // stage: kh|kl|vh|vl = 36864
#define ATT_SMEM (2 * AQ_BYTES + 3 * AST)  // 36864 + 110592 = 147456

__device__ __forceinline__ void att_load_kv(
    uint32_t base, const bf* khp, const bf* klp, const bf* vhp, const bf* vlp,
    int kt, int tid)
{
    #pragma unroll
    for (int i = 0; i < 2; i++) {
        int c = i * 256 + tid;
        int row = c >> 3, col = c & 7;
        uint32_t so = (uint32_t)(row * AROW + col * 16);
        size_t g = (size_t)(kt * 64 + row) * HDIM + col * 8;
        CP16(base + so,                   khp + g);
        CP16(base + AKV_BYTES + so,       klp + g);
        CP16(base + 2 * AKV_BYTES + so,   vhp + g);
        CP16(base + 3 * AKV_BYTES + so,   vlp + g);
    }
}

__global__ __launch_bounds__(256) void flash_hmma(
    const bf* __restrict__ qh, const bf* __restrict__ ql,
    const bf* __restrict__ kh, const bf* __restrict__ kl,
    const bf* __restrict__ vh, const bf* __restrict__ vl,
    bf* __restrict__ chi, bf* __restrict__ clo)
{
    extern __shared__ __align__(128) char asmbuf[];
    const uint32_t sb = smem_u32(asmbuf);
    const int tid = threadIdx.x, wid = tid >> 5, lane = tid & 31;
    const int qt = 15 - (int)blockIdx.x;      // longest first
    const int h = blockIdx.y, b = blockIdx.z;
    const int q0 = qt * 128;
    const int ktmax = 2 * qt + 1;

    const size_t headoff = ((size_t)b * NHEAD + h) * SEQ * HDIM;
    const bf* qhp = qh + headoff + (size_t)q0 * HDIM;
    const bf* qlp = ql + headoff + (size_t)q0 * HDIM;
    const bf* khp = kh + headoff;
    const bf* klp = kl + headoff;
    const bf* vhp = vh + headoff;
    const bf* vlp = vl + headoff;

    // load Q tiles (hi/lo)
    #pragma unroll
    for (int i = 0; i < 4; i++) {
        int c = i * 256 + tid;
        int row = c >> 3, col = c & 7;
        uint32_t so = (uint32_t)(row * AROW + col * 16);
        size_t g = (size_t)row * HDIM + col * 8;
        CP16(sb + so,            qhp + g);
        CP16(sb + AQ_BYTES + so, qlp + g);
    }
    att_load_kv(sb + 2 * AQ_BYTES, khp, klp, vhp, vlp, 0, tid);
    CP_COMMIT();                                   // G0: Q + stage0
    att_load_kv(sb + 2 * AQ_BYTES + AST, khp, klp, vhp, vlp, 1, tid);
    CP_COMMIT();                                   // G1: stage1 (ktmax >= 1 always)

    float s[8][4], acc[8][4];
    float m0v = -1e30f, m1v = -1e30f, l0v = 0.f, l1v = 0.f;
    #pragma unroll
    for (int nc = 0; nc < 8; nc++) {
        acc[nc][0] = acc[nc][1] = acc[nc][2] = acc[nc][3] = 0.f;
    }
    uint32_t qfh[16], qfl[16];

    const uint32_t a_off = (uint32_t)((wid * 16 + (lane & 15)) * AROW + (lane >> 4) * 16);
    const uint32_t kb_off = (uint32_t)(((lane >> 4) * 8 + (lane & 7)) * AROW
                                       + (((lane & 15) >> 3) * 16));
    const uint32_t vb_off = (uint32_t)((lane & 15) * AROW + (lane >> 4) * 16);

    for (int kt = 0; kt <= ktmax; kt++) {
        if (kt < ktmax) { CP_WAIT1(); } else { CP_WAIT0(); }
        __syncthreads();

        if (kt == 0) {   // Q resident now; load A fragments once
            #pragma unroll
            for (int ks = 0; ks < 4; ks++) {
                ldsm4(&qfh[ks * 4], sb + a_off + (uint32_t)(ks * 32));
                ldsm4(&qfl[ks * 4], sb + AQ_BYTES + a_off + (uint32_t)(ks * 32));
            }
        }
        int t = kt + 2;
        if (t <= ktmax) {
            att_load_kv(sb + 2 * AQ_BYTES + (uint32_t)(t % 3) * AST,
                        khp, klp, vhp, vlp, t, tid);
            CP_COMMIT();
        }
        const uint32_t kvb = sb + 2 * AQ_BYTES + (uint32_t)(kt % 3) * AST;

        // ---- scores = Q K^T (3-MMA split), pre-scaled ----
        #pragma unroll
        for (int nc = 0; nc < 8; nc++) {
            s[nc][0] = s[nc][1] = s[nc][2] = s[nc][3] = 0.f;
        }
        #pragma unroll
        for (int ks = 0; ks < 4; ks++) {
            uint32_t kf[4][4], kg[4][4];
            #pragma unroll
            for (int g = 0; g < 4; g++) {
                uint32_t ad = kvb + kb_off + (uint32_t)(g * 16 * AROW) + (uint32_t)(ks * 32);
                ldsm4(kf[g], ad);
                ldsm4(kg[g], ad + AKV_BYTES);
            }
            #pragma unroll
            for (int nc = 0; nc < 8; nc++) {
                const uint32_t* bh_ = &kf[nc >> 1][(nc & 1) * 2];
                const uint32_t* bl_ = &kg[nc >> 1][(nc & 1) * 2];
                mma16816(s[nc], &qfh[ks * 4], bh_);
                mma16816(s[nc], &qfl[ks * 4], bh_);
                mma16816(s[nc], &qfh[ks * 4], bl_);
            }
        }

        // ---- online softmax ----
        if (kt >= 2 * qt) {   // diagonal tiles: elementwise causal mask
            const int keyb = kt * 64 + 2 * (lane & 3);
            const int r0 = q0 + wid * 16 + (lane >> 2);
            #pragma unroll
            for (int nc = 0; nc < 8; nc++) {
                int k0 = keyb + nc * 8;
                if (k0     > r0)     s[nc][0] = -1e30f;
                if (k0 + 1 > r0)     s[nc][1] = -1e30f;
                if (k0     > r0 + 8) s[nc][2] = -1e30f;
                if (k0 + 1 > r0 + 8) s[nc][3] = -1e30f;
            }
        }
        float mx0 = -1e30f, mx1 = -1e30f;
        #pragma unroll
        for (int nc = 0; nc < 8; nc++) {
            mx0 = fmaxf(mx0, fmaxf(s[nc][0], s[nc][1]));
            mx1 = fmaxf(mx1, fmaxf(s[nc][2], s[nc][3]));
        }
        mx0 = fmaxf(mx0, __shfl_xor_sync(0xffffffffu, mx0, 1));
        mx0 = fmaxf(mx0, __shfl_xor_sync(0xffffffffu, mx0, 2));
        mx1 = fmaxf(mx1, __shfl_xor_sync(0xffffffffu, mx1, 1));
        mx1 = fmaxf(mx1, __shfl_xor_sync(0xffffffffu, mx1, 2));
        float mn0 = fmaxf(m0v, mx0), mn1 = fmaxf(m1v, mx1);
        float c0 = __expf(m0v - mn0), c1 = __expf(m1v - mn1);
        float su0 = 0.f, su1 = 0.f;
        #pragma unroll
        for (int nc = 0; nc < 8; nc++) {
            s[nc][0] = __expf(s[nc][0] - mn0);
            s[nc][1] = __expf(s[nc][1] - mn0);
            s[nc][2] = __expf(s[nc][2] - mn1);
            s[nc][3] = __expf(s[nc][3] - mn1);
            su0 += s[nc][0] + s[nc][1];
            su1 += s[nc][2] + s[nc][3];
        }
        su0 += __shfl_xor_sync(0xffffffffu, su0, 1);
        su0 += __shfl_xor_sync(0xffffffffu, su0, 2);
        su1 += __shfl_xor_sync(0xffffffffu, su1, 1);
        su1 += __shfl_xor_sync(0xffffffffu, su1, 2);
        l0v = l0v * c0 + su0;
        l1v = l1v * c1 + su1;
        m0v = mn0; m1v = mn1;
        #pragma unroll
        for (int nc = 0; nc < 8; nc++) {
            acc[nc][0] *= c0; acc[nc][1] *= c0;
            acc[nc][2] *= c1; acc[nc][3] *= c1;
        }

        // ---- ctx += P V (3-MMA split); P frags straight from score regs ----
        #pragma unroll
        for (int ks = 0; ks < 4; ks++) {
            uint32_t ph[4], pl[4];
            split2(s[2 * ks][0],     s[2 * ks][1],     ph[0], pl[0]);
            split2(s[2 * ks][2],     s[2 * ks][3],     ph[1], pl[1]);
            split2(s[2 * ks + 1][0], s[2 * ks + 1][1], ph[2], pl[2]);
            split2(s[2 * ks + 1][2], s[2 * ks + 1][3], ph[3], pl[3]);
            uint32_t vf[4][4], vg[4][4];
            #pragma unroll
            for (int g = 0; g < 4; g++) {
                uint32_t ad = kvb + 2 * AKV_BYTES + vb_off
                            + (uint32_t)(ks * 16 * AROW) + (uint32_t)(g * 32);
                ldsm4t(vf[g], ad);
                ldsm4t(vg[g], ad + AKV_BYTES);
            }
            #pragma unroll
            for (int nc = 0; nc < 8; nc++) {
                const uint32_t* bh_ = &vf[nc >> 1][(nc & 1) * 2];
                const uint32_t* bl_ = &vg[nc >> 1][(nc & 1) * 2];
                mma16816(acc[nc], ph, bh_);
                mma16816(acc[nc], pl, bh_);
                mma16816(acc[nc], ph, bl_);
            }
        }
    }

    // ---- epilogue: normalize + write ctx hi/lo ----
    float i0 = 1.f / l0v, i1 = 1.f / l1v;
    const int r0 = q0 + wid * 16 + (lane >> 2);
    const int cb = h * HDIM + 2 * (lane & 3);
    #pragma unroll
    for (int nc = 0; nc < 8; nc++) {
        int cc = cb + nc * 8;
        uint32_t ph, pl;
        split2(acc[nc][0] * i0, acc[nc][1] * i0, ph, pl);
        size_t off = (size_t)(b * SEQ + r0) * DMODEL + cc;
        *(uint32_t*)(chi + off) = ph;
        *(uint32_t*)(clo + off) = pl;
        split2(acc[nc][2] * i1, acc[nc][3] * i1, ph, pl);
        off = (size_t)(b * SEQ + r0 + 8) * DMODEL + cc;
        *(uint32_t*)(chi + off) = ph;
        *(uint32_t*)(clo + off) = pl;
    }
}

// ---------------------------------------------------------------------------
extern "C" void kernel_launch(void* const* d_in, const int* in_sizes, int n_in,
                              void* d_out, int out_size)
{
    (void)in_sizes; (void)n_in; (void)out_size;
    const float* x     = (const float*)d_in[0];
    const float* W_qkv = (const float*)d_in[1];
    const float* b_qkv = (const float*)d_in[2];
    const float* W_out = (const float*)d_in[3];
    float* out = (float*)d_out;

    bf *xhi, *xlo, *wqh, *wql, *woh, *wol, *chi, *clo;
    bf *qh, *ql, *kh, *kl, *vh, *vl;
    cudaGetSymbolAddress((void**)&xhi, g_xhi);
    cudaGetSymbolAddress((void**)&xlo, g_xlo);
    cudaGetSymbolAddress((void**)&wqh, g_wqh);
    cudaGetSymbolAddress((void**)&wql, g_wql);
    cudaGetSymbolAddress((void**)&woh, g_woh);
    cudaGetSymbolAddress((void**)&wol, g_wol);
    cudaGetSymbolAddress((void**)&chi, g_chi);
    cudaGetSymbolAddress((void**)&clo, g_clo);
    cudaGetSymbolAddress((void**)&qh, g_qh);
    cudaGetSymbolAddress((void**)&ql, g_ql);
    cudaGetSymbolAddress((void**)&kh, g_kh);
    cudaGetSymbolAddress((void**)&kl, g_kl);
    cudaGetSymbolAddress((void**)&vh, g_vh);
    cudaGetSymbolAddress((void**)&vl, g_vl);

    cudaFuncSetAttribute(gemm_hmma_x3<0>, cudaFuncAttributeMaxDynamicSharedMemorySize,
                         GM_DYN_BYTES);
    cudaFuncSetAttribute(gemm_hmma_x3<1>, cudaFuncAttributeMaxDynamicSharedMemorySize,
                         GM_DYN_BYTES);
    cudaFuncSetAttribute(flash_hmma, cudaFuncAttributeMaxDynamicSharedMemorySize,
                         ATT_SMEM);

    // pre-pass: decompose x (elementwise) and weights (transpose + split)
    decomp_kernel<<<(ROWS * DMODEL / 4 + 255) / 256, 256>>>(x, xhi, xlo, ROWS * DMODEL / 4);
    tdecomp_kernel<<<dim3(QKV_N / 32, DMODEL / 32), dim3(32, 8)>>>(W_qkv, wqh, wql, DMODEL, QKV_N);
    tdecomp_kernel<<<dim3(DMODEL / 32, DMODEL / 32), dim3(32, 8)>>>(W_out, woh, wol, DMODEL, DMODEL);

    // 1) QKV projection with fused split/scatter epilogue (scale folded into q)
    gemm_hmma_x3<1><<<dim3(QKV_N / 128, ROWS / 128), 256, GM_DYN_BYTES>>>(
        xhi, xlo, wqh, wql, b_qkv, nullptr,
        qh, ql, kh, kl, vh, vl, ROWS, QKV_N, DMODEL);

    // 2) causal flash attention on tensor cores (writes ctx hi/lo)
    flash_hmma<<<dim3(16, NHEAD, BATCH), 256, ATT_SMEM>>>(
        qh, ql, kh, kl, vh, vl, chi, clo);

    // 3) output projection -> fp32 out
    gemm_hmma_x3<0><<<dim3(DMODEL / 128, ROWS / 128), 256, GM_DYN_BYTES>>>(
        chi, clo, woh, wol, nullptr, out,
        nullptr, nullptr, nullptr, nullptr, nullptr, nullptr,
        ROWS, DMODEL, DMODEL);
}

// round 5
// speedup vs baseline: 2.5106x; 1.0633x over previous
#include <cuda_runtime.h>
#include <cuda_bf16.h>
#include <math.h>
#include <stdint.h>

#define BATCH 2
#define SEQ   2048
#define DMODEL 1024
#define NHEAD 16
#define HDIM  64
#define ROWS  (BATCH*SEQ)          // 4096
#define QKV_N (3*DMODEL)           // 3072

typedef __nv_bfloat16 bf;

// ---------------------------------------------------------------------------
// Device scratch
// ---------------------------------------------------------------------------
__device__ bf g_xhi[(size_t)ROWS * DMODEL];
__device__ bf g_xlo[(size_t)ROWS * DMODEL];
__device__ bf g_wqh[(size_t)QKV_N * DMODEL];   // W_qkv^T [3072][1024]
__device__ bf g_wql[(size_t)QKV_N * DMODEL];
__device__ bf g_woh[(size_t)DMODEL * DMODEL];  // W_out^T [1024][1024]
__device__ bf g_wol[(size_t)DMODEL * DMODEL];
__device__ bf g_chi[(size_t)ROWS * DMODEL];    // ctx hi/lo [row][1024]
__device__ bf g_clo[(size_t)ROWS * DMODEL];
// q/k/v split, layout [b][h][s][d]
__device__ bf g_qh[(size_t)BATCH * NHEAD * SEQ * HDIM];
__device__ bf g_ql[(size_t)BATCH * NHEAD * SEQ * HDIM];
__device__ bf g_kh[(size_t)BATCH * NHEAD * SEQ * HDIM];
__device__ bf g_kl[(size_t)BATCH * NHEAD * SEQ * HDIM];
__device__ bf g_vh[(size_t)BATCH * NHEAD * SEQ * HDIM];
__device__ bf g_vl[(size_t)BATCH * NHEAD * SEQ * HDIM];

// ---------------------------------------------------------------------------
// PTX helpers
// ---------------------------------------------------------------------------
__device__ __forceinline__ uint32_t smem_u32(const void* p) {
    uint32_t a;
    asm("{ .reg .u64 t; cvta.to.shared.u64 t, %1; cvt.u32.u64 %0, t; }" : "=r"(a) : "l"(p));
    return a;
}
#define CP16(sm, gm) asm volatile("cp.async.cg.shared.global [%0], [%1], 16;" :: "r"(sm), "l"(gm))
#define CP_COMMIT()  asm volatile("cp.async.commit_group;" ::: "memory")
#define CP_WAIT2()   asm volatile("cp.async.wait_group 2;" ::: "memory")
#define CP_WAIT1()   asm volatile("cp.async.wait_group 1;" ::: "memory")
#define CP_WAIT0()   asm volatile("cp.async.wait_group 0;" ::: "memory")

__device__ __forceinline__ void ldsm4(uint32_t* r, uint32_t addr) {
    asm volatile("ldmatrix.sync.aligned.m8n8.x4.shared.b16 {%0,%1,%2,%3}, [%4];"
                 : "=r"(r[0]), "=r"(r[1]), "=r"(r[2]), "=r"(r[3]) : "r"(addr));
}
__device__ __forceinline__ void ldsm4t(uint32_t* r, uint32_t addr) {
    asm volatile("ldmatrix.sync.aligned.m8n8.x4.trans.shared.b16 {%0,%1,%2,%3}, [%4];"
                 : "=r"(r[0]), "=r"(r[1]), "=r"(r[2]), "=r"(r[3]) : "r"(addr));
}
__device__ __forceinline__ void mma16816(float* c, const uint32_t* a, const uint32_t* b) {
    asm volatile(
        "mma.sync.aligned.m16n8k16.row.col.f32.bf16.bf16.f32 "
        "{%0,%1,%2,%3}, {%4,%5,%6,%7}, {%8,%9}, {%0,%1,%2,%3};"
        : "+f"(c[0]), "+f"(c[1]), "+f"(c[2]), "+f"(c[3])
        : "r"(a[0]), "r"(a[1]), "r"(a[2]), "r"(a[3]), "r"(b[0]), "r"(b[1]));
}
__device__ __forceinline__ uint32_t packbf(float x, float y) {
    __nv_bfloat162 t = __float22bfloat162_rn(make_float2(x, y));  // x -> low half
    return *(uint32_t*)&t;
}
__device__ __forceinline__ void split2(float x, float y, uint32_t& h, uint32_t& l) {
    h = packbf(x, y);
    float hx = __uint_as_float(h << 16);
    float hy = __uint_as_float(h & 0xffff0000u);
    l = packbf(x - hx, y - hy);
}

// ---------------------------------------------------------------------------
// Pre-pass kernels
// ---------------------------------------------------------------------------
__global__ __launch_bounds__(256) void decomp_kernel(
    const float* __restrict__ s, bf* __restrict__ hi, bf* __restrict__ lo, int n4)
{
    int i = blockIdx.x * 256 + threadIdx.x;
    if (i >= n4) return;
    float4 v = ((const float4*)s)[i];
    uint32_t h0, l0, h1, l1;
    split2(v.x, v.y, h0, l0);
    split2(v.z, v.w, h1, l1);
    *(uint2*)(hi + 4 * (size_t)i) = make_uint2(h0, h1);
    *(uint2*)(lo + 4 * (size_t)i) = make_uint2(l0, l1);
}

__global__ __launch_bounds__(256) void tdecomp_kernel(
    const float* __restrict__ W, bf* __restrict__ hi, bf* __restrict__ lo, int K, int N)
{
    __shared__ float t[32][33];
    const int tx = threadIdx.x, ty = threadIdx.y;   // 32 x 8
    const int n0 = blockIdx.x * 32, k0 = blockIdx.y * 32;
    #pragma unroll
    for (int i = 0; i < 4; i++)
        t[ty + i * 8][tx] = W[(size_t)(k0 + ty + i * 8) * N + n0 + tx];
    __syncthreads();
    #pragma unroll
    for (int i = 0; i < 4; i++) {
        float v = t[tx][ty + i * 8];
        bf h = __float2bfloat16(v);
        bf l = __float2bfloat16(v - __bfloat162float(h));
        size_t o = (size_t)(n0 + ty + i * 8) * K + k0 + tx;
        hi[o] = h; lo[o] = l;
    }
}

// ---------------------------------------------------------------------------
// Tensor-core GEMM via mma.sync, bf16 3-MMA split.
// 512 threads, 16 warps (4x4), warp tile 32x32, BK=32, 4-stage cp.async ring,
// ONE __syncthreads per iteration (issue-after-barrier ordering).
// EPI=0: fp32 C. EPI=1: fused QKV split/scatter epilogue.
// ---------------------------------------------------------------------------
#define GK 32
#define GROW 80
#define GSUB (128 * GROW)
#define GSTAGE (4 * GSUB)     // 40960
#define GNBUF 4
#define GM_DYN_BYTES (GNBUF * GSTAGE + 256)

__device__ __forceinline__ void gm_load_stage(
    uint32_t buf, const bf* gah, const bf* gal, const bf* gbh, const bf* gbl,
    int K, int tid)
{
    // 512 chunks of 16B per sub-matrix; 512 threads -> 1 chunk each
    int row = tid >> 2, col = tid & 3;
    uint32_t so = (uint32_t)(row * GROW + col * 16);
    size_t g = (size_t)row * K + (size_t)col * 8;
    CP16(buf + so,            gah + g);
    CP16(buf + GSUB + so,     gal + g);
    CP16(buf + 2 * GSUB + so, gbh + g);
    CP16(buf + 3 * GSUB + so, gbl + g);
}

template<int EPI>
__global__ __launch_bounds__(512, 1) void gemm_hmma_x3(
    const bf* __restrict__ Ah, const bf* __restrict__ Al,
    const bf* __restrict__ Bh, const bf* __restrict__ Bl,
    const float* __restrict__ bias, float* __restrict__ C,
    bf* __restrict__ oqh, bf* __restrict__ oql,
    bf* __restrict__ okh, bf* __restrict__ okl,
    bf* __restrict__ ovh, bf* __restrict__ ovl,
    int M, int N, int K)
{
    extern __shared__ __align__(128) char dynsm[];
    const uint32_t smbase = smem_u32(dynsm);

    const int tid = threadIdx.x;
    const int wid = tid >> 5, lane = tid & 31;
    const int wr = wid >> 2, wc = wid & 3;          // warp grid 4 x 4
    const int m0 = blockIdx.y * 128, n0 = blockIdx.x * 128;

    const bf* ah0 = Ah + (size_t)m0 * K;
    const bf* al0 = Al + (size_t)m0 * K;
    const bf* bh0 = Bh + (size_t)n0 * K;
    const bf* bl0 = Bl + (size_t)n0 * K;

    // warp tile 32x32: A rows wr*32..+31 (2 tiles of 16), B rows wc*32..+31
    const uint32_t a_off = (uint32_t)((wr * 32 + (lane & 15)) * GROW + (lane >> 4) * 16);
    const uint32_t b_off = (uint32_t)((wc * 32 + (lane >> 4) * 8 + (lane & 7)) * GROW
                                      + (((lane & 15) >> 3) * 16));

    float acc[2][4][4];
    #pragma unroll
    for (int i = 0; i < 2; i++)
        #pragma unroll
        for (int j = 0; j < 4; j++)
            #pragma unroll
            for (int r = 0; r < 4; r++) acc[i][j][r] = 0.f;

    const int NS = K / GK;   // 32

    // prologue: stages 0,1,2
    gm_load_stage(smbase,              ah0,          al0,          bh0,          bl0,          K, tid);
    CP_COMMIT();
    gm_load_stage(smbase + GSTAGE,     ah0 + GK,     al0 + GK,     bh0 + GK,     bl0 + GK,     K, tid);
    CP_COMMIT();
    gm_load_stage(smbase + 2 * GSTAGE, ah0 + 2 * GK, al0 + 2 * GK, bh0 + 2 * GK, bl0 + 2 * GK, K, tid);
    CP_COMMIT();

    for (int s = 0; s < NS; s++) {
        CP_WAIT2();
        __syncthreads();

        int t = s + 3;
        if (t < NS)
            gm_load_stage(smbase + (uint32_t)(t & 3) * GSTAGE,
                          ah0 + (size_t)t * GK, al0 + (size_t)t * GK,
                          bh0 + (size_t)t * GK, bl0 + (size_t)t * GK, K, tid);
        CP_COMMIT();   // empty near tail keeps wait_group accounting exact

        const uint32_t sb = smbase + (uint32_t)(s & 3) * GSTAGE;
        #pragma unroll
        for (int kk = 0; kk < 2; kk++) {
            uint32_t ah[2][4], al_[2][4], bh[2][4], bl[2][4];
            const uint32_t ko = (uint32_t)(kk * 32);
            #pragma unroll
            for (int i = 0; i < 2; i++) {
                ldsm4(ah[i],  sb + a_off + (uint32_t)(i * 16 * GROW) + ko);
                ldsm4(al_[i], sb + GSUB + a_off + (uint32_t)(i * 16 * GROW) + ko);
            }
            #pragma unroll
            for (int p = 0; p < 2; p++) {
                ldsm4(bh[p], sb + 2 * GSUB + b_off + (uint32_t)(p * 16 * GROW) + ko);
                ldsm4(bl[p], sb + 3 * GSUB + b_off + (uint32_t)(p * 16 * GROW) + ko);
            }
            #pragma unroll
            for (int i = 0; i < 2; i++)
                #pragma unroll
                for (int j = 0; j < 4; j++) {
                    const uint32_t* bhj = &bh[j >> 1][(j & 1) * 2];
                    const uint32_t* blj = &bl[j >> 1][(j & 1) * 2];
                    mma16816(acc[i][j], ah[i], bhj);
                    mma16816(acc[i][j], ah[i], blj);
                    mma16816(acc[i][j], al_[i], bhj);
                }
        }
    }

    const int er = m0 + wr * 32 + (lane >> 2);
    const int ec = n0 + wc * 32 + 2 * (lane & 3);

    if (EPI == 0) {
        #pragma unroll
        for (int i = 0; i < 2; i++)
            #pragma unroll
            for (int j = 0; j < 4; j++) {
                int r = er + i * 16, c = ec + j * 8;
                *(float2*)(C + (size_t)r * N + c) =
                    make_float2(acc[i][j][0], acc[i][j][1]);
                *(float2*)(C + (size_t)(r + 8) * N + c) =
                    make_float2(acc[i][j][2], acc[i][j][3]);
            }
    } else {
        const int part = ec >> 10;
        bf *dh, *dl;
        if (part == 0)      { dh = oqh; dl = oql; }
        else if (part == 1) { dh = okh; dl = okl; }
        else                { dh = ovh; dl = ovl; }
        const float sc = (part == 0) ? 0.125f : 1.0f;
        #pragma unroll
        for (int i = 0; i < 2; i++)
            #pragma unroll
            for (int j = 0; j < 4; j++) {
                int r = er + i * 16, c = ec + j * 8;
                int hh = (c >> 6) & 15, d = c & 63;
                float b0 = bias[c], b1 = bias[c + 1];
                uint32_t ph, pl;
                split2((acc[i][j][0] + b0) * sc, (acc[i][j][1] + b1) * sc, ph, pl);
                size_t off = (((size_t)(r >> 11) * NHEAD + hh) * SEQ + (r & 2047)) * HDIM + d;
                *(uint32_t*)(dh + off) = ph;
                *(uint32_t*)(dl + off) = pl;
                split2((acc[i][j][2] + b0) * sc, (acc[i][j][3] + b1) * sc, ph, pl);
                int r2 = r + 8;
                off = (((size_t)(r2 >> 11) * NHEAD + hh) * SEQ + (r2 & 2047)) * HDIM + d;
                *(uint32_t*)(dh + off) = ph;
                *(uint32_t*)(dl + off) = pl;
            }
    }
}

// ---------------------------------------------------------------------------
// HMMA flash attention (unchanged from R4 — validated)
// ---------------------------------------------------------------------------
#define AROW 144
#define AQ_BYTES (128 * AROW)
#define AKV_BYTES (64 * AROW)
#define AST (4 * AKV_BYTES)
#define ATT_SMEM (2 * AQ_BYTES + 3 * AST)

__device__ __forceinline__ void att_load_kv(
    uint32_t base, const bf* khp, const bf* klp, const bf* vhp, const bf* vlp,
    int kt, int tid)
{
    #pragma unroll
    for (int i = 0; i < 2; i++) {
        int c = i * 256 + tid;
        int row = c >> 3, col = c & 7;
        uint32_t so = (uint32_t)(row * AROW + col * 16);
        size_t g = (size_t)(kt * 64 + row) * HDIM + col * 8;
        CP16(base + so,                   khp + g);
        CP16(base + AKV_BYTES + so,       klp + g);
        CP16(base + 2 * AKV_BYTES + so,   vhp + g);
        CP16(base + 3 * AKV_BYTES + so,   vlp + g);
    }
}

__global__ __launch_bounds__(256) void flash_hmma(
    const bf* __restrict__ qh, const bf* __restrict__ ql,
    const bf* __restrict__ kh, const bf* __restrict__ kl,
    const bf* __restrict__ vh, const bf* __restrict__ vl,
    bf* __restrict__ chi, bf* __restrict__ clo)
{
    extern __shared__ __align__(128) char asmbuf[];
    const uint32_t sb = smem_u32(asmbuf);
    const int tid = threadIdx.x, wid = tid >> 5, lane = tid & 31;
    const int qt = 15 - (int)blockIdx.x;
    const int h = blockIdx.y, b = blockIdx.z;
    const int q0 = qt * 128;
    const int ktmax = 2 * qt + 1;

    const size_t headoff = ((size_t)b * NHEAD + h) * SEQ * HDIM;
    const bf* qhp = qh + headoff + (size_t)q0 * HDIM;
    const bf* qlp = ql + headoff + (size_t)q0 * HDIM;
    const bf* khp = kh + headoff;
    const bf* klp = kl + headoff;
    const bf* vhp = vh + headoff;
    const bf* vlp = vl + headoff;

    #pragma unroll
    for (int i = 0; i < 4; i++) {
        int c = i * 256 + tid;
        int row = c >> 3, col = c & 7;
        uint32_t so = (uint32_t)(row * AROW + col * 16);
        size_t g = (size_t)row * HDIM + col * 8;
        CP16(sb + so,            qhp + g);
        CP16(sb + AQ_BYTES + so, qlp + g);
    }
    att_load_kv(sb + 2 * AQ_BYTES, khp, klp, vhp, vlp, 0, tid);
    CP_COMMIT();
    att_load_kv(sb + 2 * AQ_BYTES + AST, khp, klp, vhp, vlp, 1, tid);
    CP_COMMIT();

    float s[8][4], acc[8][4];
    float m0v = -1e30f, m1v = -1e30f, l0v = 0.f, l1v = 0.f;
    #pragma unroll
    for (int nc = 0; nc < 8; nc++) {
        acc[nc][0] = acc[nc][1] = acc[nc][2] = acc[nc][3] = 0.f;
    }
    uint32_t qfh[16], qfl[16];

    const uint32_t a_off = (uint32_t)((wid * 16 + (lane & 15)) * AROW + (lane >> 4) * 16);
    const uint32_t kb_off = (uint32_t)(((lane >> 4) * 8 + (lane & 7)) * AROW
                                       + (((lane & 15) >> 3) * 16));
    const uint32_t vb_off = (uint32_t)((lane & 15) * AROW + (lane >> 4) * 16);

    for (int kt = 0; kt <= ktmax; kt++) {
        if (kt < ktmax) { CP_WAIT1(); } else { CP_WAIT0(); }
        __syncthreads();

        if (kt == 0) {
            #pragma unroll
            for (int ks = 0; ks < 4; ks++) {
                ldsm4(&qfh[ks * 4], sb + a_off + (uint32_t)(ks * 32));
                ldsm4(&qfl[ks * 4], sb + AQ_BYTES + a_off + (uint32_t)(ks * 32));
            }
        }
        int t = kt + 2;
        if (t <= ktmax) {
            att_load_kv(sb + 2 * AQ_BYTES + (uint32_t)(t % 3) * AST,
                        khp, klp, vhp, vlp, t, tid);
            CP_COMMIT();
        }
        const uint32_t kvb = sb + 2 * AQ_BYTES + (uint32_t)(kt % 3) * AST;

        #pragma unroll
        for (int nc = 0; nc < 8; nc++) {
            s[nc][0] = s[nc][1] = s[nc][2] = s[nc][3] = 0.f;
        }
        #pragma unroll
        for (int ks = 0; ks < 4; ks++) {
            uint32_t kf[4][4], kg[4][4];
            #pragma unroll
            for (int g = 0; g < 4; g++) {
                uint32_t ad = kvb + kb_off + (uint32_t)(g * 16 * AROW) + (uint32_t)(ks * 32);
                ldsm4(kf[g], ad);
                ldsm4(kg[g], ad + AKV_BYTES);
            }
            #pragma unroll
            for (int nc = 0; nc < 8; nc++) {
                const uint32_t* bh_ = &kf[nc >> 1][(nc & 1) * 2];
                const uint32_t* bl_ = &kg[nc >> 1][(nc & 1) * 2];
                mma16816(s[nc], &qfh[ks * 4], bh_);
                mma16816(s[nc], &qfl[ks * 4], bh_);
                mma16816(s[nc], &qfh[ks * 4], bl_);
            }
        }

        if (kt >= 2 * qt) {
            const int keyb = kt * 64 + 2 * (lane & 3);
            const int r0 = q0 + wid * 16 + (lane >> 2);
            #pragma unroll
            for (int nc = 0; nc < 8; nc++) {
                int k0 = keyb + nc * 8;
                if (k0     > r0)     s[nc][0] = -1e30f;
                if (k0 + 1 > r0)     s[nc][1] = -1e30f;
                if (k0     > r0 + 8) s[nc][2] = -1e30f;
                if (k0 + 1 > r0 + 8) s[nc][3] = -1e30f;
            }
        }
        float mx0 = -1e30f, mx1 = -1e30f;
        #pragma unroll
        for (int nc = 0; nc < 8; nc++) {
            mx0 = fmaxf(mx0, fmaxf(s[nc][0], s[nc][1]));
            mx1 = fmaxf(mx1, fmaxf(s[nc][2], s[nc][3]));
        }
        mx0 = fmaxf(mx0, __shfl_xor_sync(0xffffffffu, mx0, 1));
        mx0 = fmaxf(mx0, __shfl_xor_sync(0xffffffffu, mx0, 2));
        mx1 = fmaxf(mx1, __shfl_xor_sync(0xffffffffu, mx1, 1));
        mx1 = fmaxf(mx1, __shfl_xor_sync(0xffffffffu, mx1, 2));
        float mn0 = fmaxf(m0v, mx0), mn1 = fmaxf(m1v, mx1);
        float c0 = __expf(m0v - mn0), c1 = __expf(m1v - mn1);
        float su0 = 0.f, su1 = 0.f;
        #pragma unroll
        for (int nc = 0; nc < 8; nc++) {
            s[nc][0] = __expf(s[nc][0] - mn0);
            s[nc][1] = __expf(s[nc][1] - mn0);
            s[nc][2] = __expf(s[nc][2] - mn1);
            s[nc][3] = __expf(s[nc][3] - mn1);
            su0 += s[nc][0] + s[nc][1];
            su1 += s[nc][2] + s[nc][3];
        }
        su0 += __shfl_xor_sync(0xffffffffu, su0, 1);
        su0 += __shfl_xor_sync(0xffffffffu, su0, 2);
        su1 += __shfl_xor_sync(0xffffffffu, su1, 1);
        su1 += __shfl_xor_sync(0xffffffffu, su1, 2);
        l0v = l0v * c0 + su0;
        l1v = l1v * c1 + su1;
        m0v = mn0; m1v = mn1;
        #pragma unroll
        for (int nc = 0; nc < 8; nc++) {
            acc[nc][0] *= c0; acc[nc][1] *= c0;
            acc[nc][2] *= c1; acc[nc][3] *= c1;
        }

        #pragma unroll
        for (int ks = 0; ks < 4; ks++) {
            uint32_t ph[4], pl[4];
            split2(s[2 * ks][0],     s[2 * ks][1],     ph[0], pl[0]);
            split2(s[2 * ks][2],     s[2 * ks][3],     ph[1], pl[1]);
            split2(s[2 * ks + 1][0], s[2 * ks + 1][1], ph[2], pl[2]);
            split2(s[2 * ks + 1][2], s[2 * ks + 1][3], ph[3], pl[3]);
            uint32_t vf[4][4], vg[4][4];
            #pragma unroll
            for (int g = 0; g < 4; g++) {
                uint32_t ad = kvb + 2 * AKV_BYTES + vb_off
                            + (uint32_t)(ks * 16 * AROW) + (uint32_t)(g * 32);
                ldsm4t(vf[g], ad);
                ldsm4t(vg[g], ad + AKV_BYTES);
            }
            #pragma unroll
            for (int nc = 0; nc < 8; nc++) {
                const uint32_t* bh_ = &vf[nc >> 1][(nc & 1) * 2];
                const uint32_t* bl_ = &vg[nc >> 1][(nc & 1) * 2];
                mma16816(acc[nc], ph, bh_);
                mma16816(acc[nc], pl, bh_);
                mma16816(acc[nc], ph, bl_);
            }
        }
    }

    float i0 = 1.f / l0v, i1 = 1.f / l1v;
    const int r0 = q0 + wid * 16 + (lane >> 2);
    const int cb = h * HDIM + 2 * (lane & 3);
    #pragma unroll
    for (int nc = 0; nc < 8; nc++) {
        int cc = cb + nc * 8;
        uint32_t ph, pl;
        split2(acc[nc][0] * i0, acc[nc][1] * i0, ph, pl);
        size_t off = (size_t)(b * SEQ + r0) * DMODEL + cc;
        *(uint32_t*)(chi + off) = ph;
        *(uint32_t*)(clo + off) = pl;
        split2(acc[nc][2] * i1, acc[nc][3] * i1, ph, pl);
        off = (size_t)(b * SEQ + r0 + 8) * DMODEL + cc;
        *(uint32_t*)(chi + off) = ph;
        *(uint32_t*)(clo + off) = pl;
    }
}

// ---------------------------------------------------------------------------
extern "C" void kernel_launch(void* const* d_in, const int* in_sizes, int n_in,
                              void* d_out, int out_size)
{
    (void)in_sizes; (void)n_in; (void)out_size;
    const float* x     = (const float*)d_in[0];
    const float* W_qkv = (const float*)d_in[1];
    const float* b_qkv = (const float*)d_in[2];
    const float* W_out = (const float*)d_in[3];
    float* out = (float*)d_out;

    bf *xhi, *xlo, *wqh, *wql, *woh, *wol, *chi, *clo;
    bf *qh, *ql, *kh, *kl, *vh, *vl;
    cudaGetSymbolAddress((void**)&xhi, g_xhi);
    cudaGetSymbolAddress((void**)&xlo, g_xlo);
    cudaGetSymbolAddress((void**)&wqh, g_wqh);
    cudaGetSymbolAddress((void**)&wql, g_wql);
    cudaGetSymbolAddress((void**)&woh, g_woh);
    cudaGetSymbolAddress((void**)&wol, g_wol);
    cudaGetSymbolAddress((void**)&chi, g_chi);
    cudaGetSymbolAddress((void**)&clo, g_clo);
    cudaGetSymbolAddress((void**)&qh, g_qh);
    cudaGetSymbolAddress((void**)&ql, g_ql);
    cudaGetSymbolAddress((void**)&kh, g_kh);
    cudaGetSymbolAddress((void**)&kl, g_kl);
    cudaGetSymbolAddress((void**)&vh, g_vh);
    cudaGetSymbolAddress((void**)&vl, g_vl);

    cudaFuncSetAttribute(gemm_hmma_x3<0>, cudaFuncAttributeMaxDynamicSharedMemorySize,
                         GM_DYN_BYTES);
    cudaFuncSetAttribute(gemm_hmma_x3<1>, cudaFuncAttributeMaxDynamicSharedMemorySize,
                         GM_DYN_BYTES);
    cudaFuncSetAttribute(flash_hmma, cudaFuncAttributeMaxDynamicSharedMemorySize,
                         ATT_SMEM);

    decomp_kernel<<<(ROWS * DMODEL / 4 + 255) / 256, 256>>>(x, xhi, xlo, ROWS * DMODEL / 4);
    tdecomp_kernel<<<dim3(QKV_N / 32, DMODEL / 32), dim3(32, 8)>>>(W_qkv, wqh, wql, DMODEL, QKV_N);
    tdecomp_kernel<<<dim3(DMODEL / 32, DMODEL / 32), dim3(32, 8)>>>(W_out, woh, wol, DMODEL, DMODEL);

    gemm_hmma_x3<1><<<dim3(QKV_N / 128, ROWS / 128), 512, GM_DYN_BYTES>>>(
        xhi, xlo, wqh, wql, b_qkv, nullptr,
        qh, ql, kh, kl, vh, vl, ROWS, QKV_N, DMODEL);

    flash_hmma<<<dim3(16, NHEAD, BATCH), 256, ATT_SMEM>>>(
        qh, ql, kh, kl, vh, vl, chi, clo);

    gemm_hmma_x3<0><<<dim3(DMODEL / 128, ROWS / 128), 512, GM_DYN_BYTES>>>(
        chi, clo, woh, wol, nullptr, out,
        nullptr, nullptr, nullptr, nullptr, nullptr, nullptr,
        ROWS, DMODEL, DMODEL);
}

// round 6
// speedup vs baseline: 2.7071x; 1.0783x over previous
#include <cuda_runtime.h>
#include <cuda_bf16.h>
#include <math.h>
#include <stdint.h>

#define BATCH 2
#define SEQ   2048
#define DMODEL 1024
#define NHEAD 16
#define HDIM  64
#define ROWS  (BATCH*SEQ)          // 4096
#define QKV_N (3*DMODEL)           // 3072

typedef __nv_bfloat16 bf;

// ---------------------------------------------------------------------------
// Device scratch
// ---------------------------------------------------------------------------
__device__ bf g_xhi[(size_t)ROWS * DMODEL];
__device__ bf g_xlo[(size_t)ROWS * DMODEL];
__device__ bf g_wqh[(size_t)QKV_N * DMODEL];   // W_qkv^T [3072][1024]
__device__ bf g_wql[(size_t)QKV_N * DMODEL];
__device__ bf g_woh[(size_t)DMODEL * DMODEL];  // W_out^T [1024][1024]
__device__ bf g_wol[(size_t)DMODEL * DMODEL];
__device__ bf g_chi[(size_t)ROWS * DMODEL];    // ctx hi/lo [row][1024]
__device__ bf g_clo[(size_t)ROWS * DMODEL];
// q/k/v split, layout [b][h][s][d]
__device__ bf g_qh[(size_t)BATCH * NHEAD * SEQ * HDIM];
__device__ bf g_ql[(size_t)BATCH * NHEAD * SEQ * HDIM];
__device__ bf g_kh[(size_t)BATCH * NHEAD * SEQ * HDIM];
__device__ bf g_kl[(size_t)BATCH * NHEAD * SEQ * HDIM];
__device__ bf g_vh[(size_t)BATCH * NHEAD * SEQ * HDIM];
__device__ bf g_vl[(size_t)BATCH * NHEAD * SEQ * HDIM];

// ---------------------------------------------------------------------------
// PTX helpers
// ---------------------------------------------------------------------------
__device__ __forceinline__ uint32_t smem_u32(const void* p) {
    uint32_t a;
    asm("{ .reg .u64 t; cvta.to.shared.u64 t, %1; cvt.u32.u64 %0, t; }" : "=r"(a) : "l"(p));
    return a;
}
#define CP16(sm, gm) asm volatile("cp.async.cg.shared.global [%0], [%1], 16;" :: "r"(sm), "l"(gm))
#define CP_COMMIT()  asm volatile("cp.async.commit_group;" ::: "memory")
#define CP_WAIT2()   asm volatile("cp.async.wait_group 2;" ::: "memory")
#define CP_WAIT1()   asm volatile("cp.async.wait_group 1;" ::: "memory")
#define CP_WAIT0()   asm volatile("cp.async.wait_group 0;" ::: "memory")

__device__ __forceinline__ void ldsm4(uint32_t* r, uint32_t addr) {
    asm volatile("ldmatrix.sync.aligned.m8n8.x4.shared.b16 {%0,%1,%2,%3}, [%4];"
                 : "=r"(r[0]), "=r"(r[1]), "=r"(r[2]), "=r"(r[3]) : "r"(addr));
}
__device__ __forceinline__ void ldsm4t(uint32_t* r, uint32_t addr) {
    asm volatile("ldmatrix.sync.aligned.m8n8.x4.trans.shared.b16 {%0,%1,%2,%3}, [%4];"
                 : "=r"(r[0]), "=r"(r[1]), "=r"(r[2]), "=r"(r[3]) : "r"(addr));
}
__device__ __forceinline__ void mma16816(float* c, const uint32_t* a, const uint32_t* b) {
    asm volatile(
        "mma.sync.aligned.m16n8k16.row.col.f32.bf16.bf16.f32 "
        "{%0,%1,%2,%3}, {%4,%5,%6,%7}, {%8,%9}, {%0,%1,%2,%3};"
        : "+f"(c[0]), "+f"(c[1]), "+f"(c[2]), "+f"(c[3])
        : "r"(a[0]), "r"(a[1]), "r"(a[2]), "r"(a[3]), "r"(b[0]), "r"(b[1]));
}
__device__ __forceinline__ uint32_t packbf(float x, float y) {
    __nv_bfloat162 t = __float22bfloat162_rn(make_float2(x, y));  // x -> low half
    return *(uint32_t*)&t;
}
__device__ __forceinline__ void split2(float x, float y, uint32_t& h, uint32_t& l) {
    h = packbf(x, y);
    float hx = __uint_as_float(h << 16);
    float hy = __uint_as_float(h & 0xffff0000u);
    l = packbf(x - hx, y - hy);
}

// ---------------------------------------------------------------------------
// Pre-pass kernels
// ---------------------------------------------------------------------------
__global__ __launch_bounds__(256) void decomp_kernel(
    const float* __restrict__ s, bf* __restrict__ hi, bf* __restrict__ lo, int n4)
{
    int i = blockIdx.x * 256 + threadIdx.x;
    if (i >= n4) return;
    float4 v = ((const float4*)s)[i];
    uint32_t h0, l0, h1, l1;
    split2(v.x, v.y, h0, l0);
    split2(v.z, v.w, h1, l1);
    *(uint2*)(hi + 4 * (size_t)i) = make_uint2(h0, h1);
    *(uint2*)(lo + 4 * (size_t)i) = make_uint2(l0, l1);
}

__global__ __launch_bounds__(256) void tdecomp_kernel(
    const float* __restrict__ W, bf* __restrict__ hi, bf* __restrict__ lo, int K, int N)
{
    __shared__ float t[32][33];
    const int tx = threadIdx.x, ty = threadIdx.y;   // 32 x 8
    const int n0 = blockIdx.x * 32, k0 = blockIdx.y * 32;
    #pragma unroll
    for (int i = 0; i < 4; i++)
        t[ty + i * 8][tx] = W[(size_t)(k0 + ty + i * 8) * N + n0 + tx];
    __syncthreads();
    #pragma unroll
    for (int i = 0; i < 4; i++) {
        float v = t[tx][ty + i * 8];
        bf h = __float2bfloat16(v);
        bf l = __float2bfloat16(v - __bfloat162float(h));
        size_t o = (size_t)(n0 + ty + i * 8) * K + k0 + tx;
        hi[o] = h; lo[o] = l;
    }
}

// ---------------------------------------------------------------------------
// Tensor-core GEMM via mma.sync, bf16 3-MMA split, fragment-pipelined:
// per stage: ALL 16 ldsm + cp.async prefetch issued BEFORE the 48 MMAs.
// 512 threads, 16 warps (4x4), warp tile 32x32, BK=32, 4-stage ring.
// ---------------------------------------------------------------------------
#define GK 32
#define GROW 80
#define GSUB (128 * GROW)
#define GSTAGE (4 * GSUB)     // 40960
#define GNBUF 4
#define GM_DYN_BYTES (GNBUF * GSTAGE + 256)

__device__ __forceinline__ void gm_load_stage(
    uint32_t buf, const bf* gah, const bf* gal, const bf* gbh, const bf* gbl,
    int K, int tid)
{
    int row = tid >> 2, col = tid & 3;
    uint32_t so = (uint32_t)(row * GROW + col * 16);
    size_t g = (size_t)row * K + (size_t)col * 8;
    CP16(buf + so,            gah + g);
    CP16(buf + GSUB + so,     gal + g);
    CP16(buf + 2 * GSUB + so, gbh + g);
    CP16(buf + 3 * GSUB + so, gbl + g);
}

// fr layout: [0..7]=Ah(2 tiles), [8..15]=Al, [16..23]=Bh, [24..31]=Bl
__device__ __forceinline__ void ld_frags(uint32_t* fr, uint32_t sb,
                                         uint32_t a_off, uint32_t b_off, uint32_t ko)
{
    ldsm4(fr + 0,  sb + a_off + ko);
    ldsm4(fr + 4,  sb + a_off + 16u * GROW + ko);
    ldsm4(fr + 8,  sb + GSUB + a_off + ko);
    ldsm4(fr + 12, sb + GSUB + a_off + 16u * GROW + ko);
    ldsm4(fr + 16, sb + 2u * GSUB + b_off + ko);
    ldsm4(fr + 20, sb + 2u * GSUB + b_off + 16u * GROW + ko);
    ldsm4(fr + 24, sb + 3u * GSUB + b_off + ko);
    ldsm4(fr + 28, sb + 3u * GSUB + b_off + 16u * GROW + ko);
}

__device__ __forceinline__ void mma_frags(float acc[2][4][4], const uint32_t* fr)
{
    const uint32_t* ah = fr;
    const uint32_t* al = fr + 8;
    const uint32_t* bh = fr + 16;
    const uint32_t* bl = fr + 24;
    #pragma unroll
    for (int i = 0; i < 2; i++)
        #pragma unroll
        for (int j = 0; j < 4; j++) {
            const uint32_t* bhj = bh + (j >> 1) * 4 + (j & 1) * 2;
            const uint32_t* blj = bl + (j >> 1) * 4 + (j & 1) * 2;
            mma16816(acc[i][j], ah + i * 4, bhj);
            mma16816(acc[i][j], ah + i * 4, blj);
            mma16816(acc[i][j], al + i * 4, bhj);
        }
}

template<int EPI>
__global__ __launch_bounds__(512, 1) void gemm_hmma_x3(
    const bf* __restrict__ Ah, const bf* __restrict__ Al,
    const bf* __restrict__ Bh, const bf* __restrict__ Bl,
    const float* __restrict__ bias, float* __restrict__ C,
    bf* __restrict__ oqh, bf* __restrict__ oql,
    bf* __restrict__ okh, bf* __restrict__ okl,
    bf* __restrict__ ovh, bf* __restrict__ ovl,
    int M, int N, int K)
{
    extern __shared__ __align__(128) char dynsm[];
    const uint32_t smbase = smem_u32(dynsm);

    const int tid = threadIdx.x;
    const int wid = tid >> 5, lane = tid & 31;
    const int wr = wid >> 2, wc = wid & 3;          // warp grid 4 x 4
    const int m0 = blockIdx.y * 128, n0 = blockIdx.x * 128;

    const bf* ah0 = Ah + (size_t)m0 * K;
    const bf* al0 = Al + (size_t)m0 * K;
    const bf* bh0 = Bh + (size_t)n0 * K;
    const bf* bl0 = Bl + (size_t)n0 * K;

    const uint32_t a_off = (uint32_t)((wr * 32 + (lane & 15)) * GROW + (lane >> 4) * 16);
    const uint32_t b_off = (uint32_t)((wc * 32 + (lane >> 4) * 8 + (lane & 7)) * GROW
                                      + (((lane & 15) >> 3) * 16));

    float acc[2][4][4];
    #pragma unroll
    for (int i = 0; i < 2; i++)
        #pragma unroll
        for (int j = 0; j < 4; j++)
            #pragma unroll
            for (int r = 0; r < 4; r++) acc[i][j][r] = 0.f;

    const int NS = K / GK;   // 32

    gm_load_stage(smbase,              ah0,          al0,          bh0,          bl0,          K, tid);
    CP_COMMIT();
    gm_load_stage(smbase + GSTAGE,     ah0 + GK,     al0 + GK,     bh0 + GK,     bl0 + GK,     K, tid);
    CP_COMMIT();
    gm_load_stage(smbase + 2 * GSTAGE, ah0 + 2 * GK, al0 + 2 * GK, bh0 + 2 * GK, bl0 + 2 * GK, K, tid);
    CP_COMMIT();

    for (int s = 0; s < NS; s++) {
        CP_WAIT2();
        __syncthreads();

        const uint32_t sb = smbase + (uint32_t)(s & 3) * GSTAGE;
        uint32_t f0[32], f1[32];
        ld_frags(f0, sb, a_off, b_off, 0);     // kk0 fragments first

        int t = s + 3;                          // then global prefetch
        if (t < NS)
            gm_load_stage(smbase + (uint32_t)(t & 3) * GSTAGE,
                          ah0 + (size_t)t * GK, al0 + (size_t)t * GK,
                          bh0 + (size_t)t * GK, bl0 + (size_t)t * GK, K, tid);
        CP_COMMIT();

        ld_frags(f1, sb, a_off, b_off, 32);    // kk1 fragments before any mma

        mma_frags(acc, f0);
        mma_frags(acc, f1);
    }

    const int er = m0 + wr * 32 + (lane >> 2);
    const int ec = n0 + wc * 32 + 2 * (lane & 3);

    if (EPI == 0) {
        #pragma unroll
        for (int i = 0; i < 2; i++)
            #pragma unroll
            for (int j = 0; j < 4; j++) {
                int r = er + i * 16, c = ec + j * 8;
                *(float2*)(C + (size_t)r * N + c) =
                    make_float2(acc[i][j][0], acc[i][j][1]);
                *(float2*)(C + (size_t)(r + 8) * N + c) =
                    make_float2(acc[i][j][2], acc[i][j][3]);
            }
    } else {
        const int part = ec >> 10;
        bf *dh, *dl;
        if (part == 0)      { dh = oqh; dl = oql; }
        else if (part == 1) { dh = okh; dl = okl; }
        else                { dh = ovh; dl = ovl; }
        const float sc = (part == 0) ? 0.125f : 1.0f;
        #pragma unroll
        for (int i = 0; i < 2; i++)
            #pragma unroll
            for (int j = 0; j < 4; j++) {
                int r = er + i * 16, c = ec + j * 8;
                int hh = (c >> 6) & 15, d = c & 63;
                float b0 = bias[c], b1 = bias[c + 1];
                uint32_t ph, pl;
                split2((acc[i][j][0] + b0) * sc, (acc[i][j][1] + b1) * sc, ph, pl);
                size_t off = (((size_t)(r >> 11) * NHEAD + hh) * SEQ + (r & 2047)) * HDIM + d;
                *(uint32_t*)(dh + off) = ph;
                *(uint32_t*)(dl + off) = pl;
                split2((acc[i][j][2] + b0) * sc, (acc[i][j][3] + b1) * sc, ph, pl);
                int r2 = r + 8;
                off = (((size_t)(r2 >> 11) * NHEAD + hh) * SEQ + (r2 & 2047)) * HDIM + d;
                *(uint32_t*)(dh + off) = ph;
                *(uint32_t*)(dl + off) = pl;
            }
    }
}

// ---------------------------------------------------------------------------
// HMMA flash attention with fragment double-buffering in QK and PV loops.
// ---------------------------------------------------------------------------
#define AROW 144
#define AQ_BYTES (128 * AROW)
#define AKV_BYTES (64 * AROW)
#define AST (4 * AKV_BYTES)
#define ATT_SMEM (2 * AQ_BYTES + 3 * AST)

__device__ __forceinline__ void att_load_kv(
    uint32_t base, const bf* khp, const bf* klp, const bf* vhp, const bf* vlp,
    int kt, int tid)
{
    #pragma unroll
    for (int i = 0; i < 2; i++) {
        int c = i * 256 + tid;
        int row = c >> 3, col = c & 7;
        uint32_t so = (uint32_t)(row * AROW + col * 16);
        size_t g = (size_t)(kt * 64 + row) * HDIM + col * 8;
        CP16(base + so,                   khp + g);
        CP16(base + AKV_BYTES + so,       klp + g);
        CP16(base + 2 * AKV_BYTES + so,   vhp + g);
        CP16(base + 3 * AKV_BYTES + so,   vlp + g);
    }
}

// f[0..15] = hi-fragments (4 ldsm), f[16..31] = lo-fragments
__device__ __forceinline__ void ld_kfr(uint32_t* f, uint32_t kvb, uint32_t kb_off, int ks)
{
    #pragma unroll
    for (int g = 0; g < 4; g++) {
        uint32_t ad = kvb + kb_off + (uint32_t)(g * 16 * AROW) + (uint32_t)(ks * 32);
        ldsm4(f + g * 4, ad);
        ldsm4(f + 16 + g * 4, ad + AKV_BYTES);
    }
}
__device__ __forceinline__ void ld_vfr(uint32_t* f, uint32_t kvb, uint32_t vb_off, int ks)
{
    #pragma unroll
    for (int g = 0; g < 4; g++) {
        uint32_t ad = kvb + 2 * AKV_BYTES + vb_off
                    + (uint32_t)(ks * 16 * AROW) + (uint32_t)(g * 32);
        ldsm4t(f + g * 4, ad);
        ldsm4t(f + 16 + g * 4, ad + AKV_BYTES);
    }
}

__global__ __launch_bounds__(256) void flash_hmma(
    const bf* __restrict__ qh, const bf* __restrict__ ql,
    const bf* __restrict__ kh, const bf* __restrict__ kl,
    const bf* __restrict__ vh, const bf* __restrict__ vl,
    bf* __restrict__ chi, bf* __restrict__ clo)
{
    extern __shared__ __align__(128) char asmbuf[];
    const uint32_t sb = smem_u32(asmbuf);
    const int tid = threadIdx.x, wid = tid >> 5, lane = tid & 31;
    const int qt = 15 - (int)blockIdx.x;
    const int h = blockIdx.y, b = blockIdx.z;
    const int q0 = qt * 128;
    const int ktmax = 2 * qt + 1;

    const size_t headoff = ((size_t)b * NHEAD + h) * SEQ * HDIM;
    const bf* qhp = qh + headoff + (size_t)q0 * HDIM;
    const bf* qlp = ql + headoff + (size_t)q0 * HDIM;
    const bf* khp = kh + headoff;
    const bf* klp = kl + headoff;
    const bf* vhp = vh + headoff;
    const bf* vlp = vl + headoff;

    #pragma unroll
    for (int i = 0; i < 4; i++) {
        int c = i * 256 + tid;
        int row = c >> 3, col = c & 7;
        uint32_t so = (uint32_t)(row * AROW + col * 16);
        size_t g = (size_t)row * HDIM + col * 8;
        CP16(sb + so,            qhp + g);
        CP16(sb + AQ_BYTES + so, qlp + g);
    }
    att_load_kv(sb + 2 * AQ_BYTES, khp, klp, vhp, vlp, 0, tid);
    CP_COMMIT();
    att_load_kv(sb + 2 * AQ_BYTES + AST, khp, klp, vhp, vlp, 1, tid);
    CP_COMMIT();

    float s[8][4], acc[8][4];
    float m0v = -1e30f, m1v = -1e30f, l0v = 0.f, l1v = 0.f;
    #pragma unroll
    for (int nc = 0; nc < 8; nc++) {
        acc[nc][0] = acc[nc][1] = acc[nc][2] = acc[nc][3] = 0.f;
    }
    uint32_t qfh[16], qfl[16];

    const uint32_t a_off = (uint32_t)((wid * 16 + (lane & 15)) * AROW + (lane >> 4) * 16);
    const uint32_t kb_off = (uint32_t)(((lane >> 4) * 8 + (lane & 7)) * AROW
                                       + (((lane & 15) >> 3) * 16));
    const uint32_t vb_off = (uint32_t)((lane & 15) * AROW + (lane >> 4) * 16);

    for (int kt = 0; kt <= ktmax; kt++) {
        if (kt < ktmax) { CP_WAIT1(); } else { CP_WAIT0(); }
        __syncthreads();

        if (kt == 0) {
            #pragma unroll
            for (int ks = 0; ks < 4; ks++) {
                ldsm4(&qfh[ks * 4], sb + a_off + (uint32_t)(ks * 32));
                ldsm4(&qfl[ks * 4], sb + AQ_BYTES + a_off + (uint32_t)(ks * 32));
            }
        }
        int t = kt + 2;
        if (t <= ktmax) {
            att_load_kv(sb + 2 * AQ_BYTES + (uint32_t)(t % 3) * AST,
                        khp, klp, vhp, vlp, t, tid);
            CP_COMMIT();
        }
        const uint32_t kvb = sb + 2 * AQ_BYTES + (uint32_t)(kt % 3) * AST;

        // ---- scores = Q K^T (3-MMA split), K-fragments double-buffered ----
        #pragma unroll
        for (int nc = 0; nc < 8; nc++) {
            s[nc][0] = s[nc][1] = s[nc][2] = s[nc][3] = 0.f;
        }
        {
            uint32_t kfb[2][32];
            ld_kfr(kfb[0], kvb, kb_off, 0);
            #pragma unroll
            for (int ks = 0; ks < 4; ks++) {
                if (ks < 3) ld_kfr(kfb[(ks + 1) & 1], kvb, kb_off, ks + 1);
                const uint32_t* kf = kfb[ks & 1];
                const uint32_t* kg = kf + 16;
                #pragma unroll
                for (int nc = 0; nc < 8; nc++) {
                    const uint32_t* bh_ = kf + (nc >> 1) * 4 + (nc & 1) * 2;
                    const uint32_t* bl_ = kg + (nc >> 1) * 4 + (nc & 1) * 2;
                    mma16816(s[nc], &qfh[ks * 4], bh_);
                    mma16816(s[nc], &qfl[ks * 4], bh_);
                    mma16816(s[nc], &qfh[ks * 4], bl_);
                }
            }
        }

        // ---- online softmax ----
        if (kt >= 2 * qt) {
            const int keyb = kt * 64 + 2 * (lane & 3);
            const int r0 = q0 + wid * 16 + (lane >> 2);
            #pragma unroll
            for (int nc = 0; nc < 8; nc++) {
                int k0 = keyb + nc * 8;
                if (k0     > r0)     s[nc][0] = -1e30f;
                if (k0 + 1 > r0)     s[nc][1] = -1e30f;
                if (k0     > r0 + 8) s[nc][2] = -1e30f;
                if (k0 + 1 > r0 + 8) s[nc][3] = -1e30f;
            }
        }
        float mx0 = -1e30f, mx1 = -1e30f;
        #pragma unroll
        for (int nc = 0; nc < 8; nc++) {
            mx0 = fmaxf(mx0, fmaxf(s[nc][0], s[nc][1]));
            mx1 = fmaxf(mx1, fmaxf(s[nc][2], s[nc][3]));
        }
        mx0 = fmaxf(mx0, __shfl_xor_sync(0xffffffffu, mx0, 1));
        mx0 = fmaxf(mx0, __shfl_xor_sync(0xffffffffu, mx0, 2));
        mx1 = fmaxf(mx1, __shfl_xor_sync(0xffffffffu, mx1, 1));
        mx1 = fmaxf(mx1, __shfl_xor_sync(0xffffffffu, mx1, 2));
        float mn0 = fmaxf(m0v, mx0), mn1 = fmaxf(m1v, mx1);
        float c0 = __expf(m0v - mn0), c1 = __expf(m1v - mn1);
        float su0 = 0.f, su1 = 0.f;
        #pragma unroll
        for (int nc = 0; nc < 8; nc++) {
            s[nc][0] = __expf(s[nc][0] - mn0);
            s[nc][1] = __expf(s[nc][1] - mn0);
            s[nc][2] = __expf(s[nc][2] - mn1);
            s[nc][3] = __expf(s[nc][3] - mn1);
            su0 += s[nc][0] + s[nc][1];
            su1 += s[nc][2] + s[nc][3];
        }
        su0 += __shfl_xor_sync(0xffffffffu, su0, 1);
        su0 += __shfl_xor_sync(0xffffffffu, su0, 2);
        su1 += __shfl_xor_sync(0xffffffffu, su1, 1);
        su1 += __shfl_xor_sync(0xffffffffu, su1, 2);
        l0v = l0v * c0 + su0;
        l1v = l1v * c1 + su1;
        m0v = mn0; m1v = mn1;
        #pragma unroll
        for (int nc = 0; nc < 8; nc++) {
            acc[nc][0] *= c0; acc[nc][1] *= c0;
            acc[nc][2] *= c1; acc[nc][3] *= c1;
        }

        // ---- ctx += P V (3-MMA split), V-fragments double-buffered ----
        {
            uint32_t vfb[2][32];
            ld_vfr(vfb[0], kvb, vb_off, 0);
            #pragma unroll
            for (int ks = 0; ks < 4; ks++) {
                if (ks < 3) ld_vfr(vfb[(ks + 1) & 1], kvb, vb_off, ks + 1);
                uint32_t ph[4], pl[4];
                split2(s[2 * ks][0],     s[2 * ks][1],     ph[0], pl[0]);
                split2(s[2 * ks][2],     s[2 * ks][3],     ph[1], pl[1]);
                split2(s[2 * ks + 1][0], s[2 * ks + 1][1], ph[2], pl[2]);
                split2(s[2 * ks + 1][2], s[2 * ks + 1][3], ph[3], pl[3]);
                const uint32_t* vf = vfb[ks & 1];
                const uint32_t* vg = vf + 16;
                #pragma unroll
                for (int nc = 0; nc < 8; nc++) {
                    const uint32_t* bh_ = vf + (nc >> 1) * 4 + (nc & 1) * 2;
                    const uint32_t* bl_ = vg + (nc >> 1) * 4 + (nc & 1) * 2;
                    mma16816(acc[nc], ph, bh_);
                    mma16816(acc[nc], pl, bh_);
                    mma16816(acc[nc], ph, bl_);
                }
            }
        }
    }

    float i0 = 1.f / l0v, i1 = 1.f / l1v;
    const int r0 = q0 + wid * 16 + (lane >> 2);
    const int cb = h * HDIM + 2 * (lane & 3);
    #pragma unroll
    for (int nc = 0; nc < 8; nc++) {
        int cc = cb + nc * 8;
        uint32_t ph, pl;
        split2(acc[nc][0] * i0, acc[nc][1] * i0, ph, pl);
        size_t off = (size_t)(b * SEQ + r0) * DMODEL + cc;
        *(uint32_t*)(chi + off) = ph;
        *(uint32_t*)(clo + off) = pl;
        split2(acc[nc][2] * i1, acc[nc][3] * i1, ph, pl);
        off = (size_t)(b * SEQ + r0 + 8) * DMODEL + cc;
        *(uint32_t*)(chi + off) = ph;
        *(uint32_t*)(clo + off) = pl;
    }
}

// ---------------------------------------------------------------------------
extern "C" void kernel_launch(void* const* d_in, const int* in_sizes, int n_in,
                              void* d_out, int out_size)
{
    (void)in_sizes; (void)n_in; (void)out_size;
    const float* x     = (const float*)d_in[0];
    const float* W_qkv = (const float*)d_in[1];
    const float* b_qkv = (const float*)d_in[2];
    const float* W_out = (const float*)d_in[3];
    float* out = (float*)d_out;

    bf *xhi, *xlo, *wqh, *wql, *woh, *wol, *chi, *clo;
    bf *qh, *ql, *kh, *kl, *vh, *vl;
    cudaGetSymbolAddress((void**)&xhi, g_xhi);
    cudaGetSymbolAddress((void**)&xlo, g_xlo);
    cudaGetSymbolAddress((void**)&wqh, g_wqh);
    cudaGetSymbolAddress((void**)&wql, g_wql);
    cudaGetSymbolAddress((void**)&woh, g_woh);
    cudaGetSymbolAddress((void**)&wol, g_wol);
    cudaGetSymbolAddress((void**)&chi, g_chi);
    cudaGetSymbolAddress((void**)&clo, g_clo);
    cudaGetSymbolAddress((void**)&qh, g_qh);
    cudaGetSymbolAddress((void**)&ql, g_ql);
    cudaGetSymbolAddress((void**)&kh, g_kh);
    cudaGetSymbolAddress((void**)&kl, g_kl);
    cudaGetSymbolAddress((void**)&vh, g_vh);
    cudaGetSymbolAddress((void**)&vl, g_vl);

    cudaFuncSetAttribute(gemm_hmma_x3<0>, cudaFuncAttributeMaxDynamicSharedMemorySize,
                         GM_DYN_BYTES);
    cudaFuncSetAttribute(gemm_hmma_x3<1>, cudaFuncAttributeMaxDynamicSharedMemorySize,
                         GM_DYN_BYTES);
    cudaFuncSetAttribute(flash_hmma, cudaFuncAttributeMaxDynamicSharedMemorySize,
                         ATT_SMEM);

    decomp_kernel<<<(ROWS * DMODEL / 4 + 255) / 256, 256>>>(x, xhi, xlo, ROWS * DMODEL / 4);
    tdecomp_kernel<<<dim3(QKV_N / 32, DMODEL / 32), dim3(32, 8)>>>(W_qkv, wqh, wql, DMODEL, QKV_N);
    tdecomp_kernel<<<dim3(DMODEL / 32, DMODEL / 32), dim3(32, 8)>>>(W_out, woh, wol, DMODEL, DMODEL);

    gemm_hmma_x3<1><<<dim3(QKV_N / 128, ROWS / 128), 512, GM_DYN_BYTES>>>(
        xhi, xlo, wqh, wql, b_qkv, nullptr,
        qh, ql, kh, kl, vh, vl, ROWS, QKV_N, DMODEL);

    flash_hmma<<<dim3(16, NHEAD, BATCH), 256, ATT_SMEM>>>(
        qh, ql, kh, kl, vh, vl, chi, clo);

    gemm_hmma_x3<0><<<dim3(DMODEL / 128, ROWS / 128), 512, GM_DYN_BYTES>>>(
        chi, clo, woh, wol, nullptr, out,
        nullptr, nullptr, nullptr, nullptr, nullptr, nullptr,
        ROWS, DMODEL, DMODEL);
}